// round 10
// baseline (speedup 1.0000x reference)
#include <cuda_runtime.h>
#include <cuda_fp16.h>
#include <cstdint>

// ---------------------------------------------------------------------------
// Problem constants
// ---------------------------------------------------------------------------
constexpr int SEQ    = 2048;
constexpr int HIDN   = 2560;
constexpr int NHEAD  = 40;
constexpr int NOPE_D = 64;
constexpr int ROPE_D = 32;
constexpr int QK_D   = NOPE_D + ROPE_D;    // 96
constexpr int V_D    = 64;
constexpr int Q_RANK = 768;
constexpr int KV_RANK= 256;
constexpr int CKV_D  = KV_RANK + ROPE_D;   // 288
constexpr int NTOK   = 2 * SEQ;            // 4096
constexpr int QD_ALL = NHEAD * QK_D;       // 3840
constexpr int KVD_ALL= NHEAD * (NOPE_D + V_D); // 5120
constexpr int OD_ALL = NHEAD * V_D;        // 2560
constexpr float SCALE = 0.10206207261596577f;
constexpr float SC2   = SCALE * 1.4426950408889634f;

// ---------------------------------------------------------------------------
// Scratch. Activations: fp16 hi only. Weights & K: hi+lo. V/wo: hi only where dropped.
// ---------------------------------------------------------------------------
__device__ __half g_hid_h [NTOK * HIDN];
__device__ __half g_wqa_h [Q_RANK * HIDN];     // transposed [N][K]
__device__ __half g_wqa_l [Q_RANK * HIDN];
__device__ __half g_wkva_h[CKV_D * HIDN];
__device__ __half g_wkva_l[CKV_D * HIDN];
__device__ __half g_wqb_h [QD_ALL * Q_RANK];
__device__ __half g_wqb_l [QD_ALL * Q_RANK];
__device__ __half g_wkvb_h[KVD_ALL * KV_RANK];
__device__ __half g_wkvb_l[KVD_ALL * KV_RANK];
__device__ __half g_wo_h  [HIDN * OD_ALL];
__device__ __half g_wo_l  [HIDN * OD_ALL];     // still produced (cheap), unused by GEMM
__device__ float  g_qa    [NTOK * Q_RANK];
__device__ float  g_ckv   [NTOK * CKV_D];
__device__ __half g_qan_h [NTOK * Q_RANK];
__device__ __half g_kvn_h [NTOK * KV_RANK];
__device__ __half g_q_h   [NTOK * QD_ALL];
__device__ __half g_kv_h  [NTOK * KVD_ALL];
__device__ __half g_kv_l  [NTOK * KVD_ALL];
__device__ __half g_kr_h  [NTOK * ROPE_D];
__device__ __half g_kr_l  [NTOK * ROPE_D];
__device__ __half g_at_h  [NTOK * OD_ALL];

// ---------------------------------------------------------------------------
// PTX helpers (portable sm_80+ subset)
// ---------------------------------------------------------------------------
__device__ __forceinline__ uint32_t smem_u32(const void* p) {
    uint32_t a;
    asm("{ .reg .u64 t; cvta.to.shared.u64 t, %1; cvt.u32.u64 %0, t; }"
        : "=r"(a) : "l"(p));
    return a;
}
__device__ __forceinline__ void ldmatrix_x4(uint32_t& r0, uint32_t& r1,
                                            uint32_t& r2, uint32_t& r3, uint32_t addr) {
    asm volatile("ldmatrix.sync.aligned.m8n8.x4.shared.b16 {%0,%1,%2,%3}, [%4];"
                 : "=r"(r0), "=r"(r1), "=r"(r2), "=r"(r3) : "r"(addr));
}
__device__ __forceinline__ void ldmatrix_x4_t(uint32_t& r0, uint32_t& r1,
                                              uint32_t& r2, uint32_t& r3, uint32_t addr) {
    asm volatile("ldmatrix.sync.aligned.m8n8.x4.trans.shared.b16 {%0,%1,%2,%3}, [%4];"
                 : "=r"(r0), "=r"(r1), "=r"(r2), "=r"(r3) : "r"(addr));
}
__device__ __forceinline__ void mma_f16(float* c, const uint32_t* a, const uint32_t* b) {
    asm volatile(
        "mma.sync.aligned.m16n8k16.row.col.f32.f16.f16.f32 "
        "{%0,%1,%2,%3}, {%4,%5,%6,%7}, {%8,%9}, {%0,%1,%2,%3};"
        : "+f"(c[0]), "+f"(c[1]), "+f"(c[2]), "+f"(c[3])
        : "r"(a[0]), "r"(a[1]), "r"(a[2]), "r"(a[3]), "r"(b[0]), "r"(b[1]));
}
#define CP16(dst, src) \
    asm volatile("cp.async.cg.shared.global [%0], [%1], 16;" :: "r"(dst), "l"(src))
#define CP16P(dst, src, pred) \
    asm volatile("cp.async.cg.shared.global [%0], [%1], 16, %2;" \
                 :: "r"(dst), "l"(src), "r"((pred) ? 16 : 0))
#define CP_COMMIT() asm volatile("cp.async.commit_group;" ::: "memory")
#define CP_WAIT(n)  asm volatile("cp.async.wait_group %0;" :: "n"(n) : "memory")

__device__ __forceinline__ uint32_t packh2(float x0, float x1) {
    uint32_t p;
    asm("cvt.rn.f16x2.f32 %0, %1, %2;" : "=r"(p) : "f"(x1), "f"(x0));
    return p;
}
__device__ __forceinline__ void splith1(float x, __half& h, __half& l) {
    h = __float2half_rn(x);
    l = __float2half_rn(x - __half2float(h));
}
__device__ __forceinline__ void splith2(float x0, float x1, uint32_t& hp, uint32_t& lp) {
    const __half h0 = __float2half_rn(x0), h1 = __float2half_rn(x1);
    hp = ((uint32_t)__half_as_ushort(h1) << 16) | (uint32_t)__half_as_ushort(h0);
    lp = packh2(x0 - __half2float(h0), x1 - __half2float(h1));
}
__device__ __forceinline__ float fexp2(float x) {
    float r;
    asm("ex2.approx.ftz.f32 %0, %1;" : "=f"(r) : "f"(x));
    return r;
}

// ---------------------------------------------------------------------------
// Prep: hidden fp32->fp16 + all weight transpose+splits, one launch
// ---------------------------------------------------------------------------
constexpr int PREP_SPLIT_BLOCKS = NTOK * HIDN / 4 / 256;  // 10240
constexpr int PREP_TOTAL_BLOCKS = PREP_SPLIT_BLOCKS + 13200;

__global__ void prep_kernel(const float* __restrict__ hidden,
                            const float* __restrict__ wqa,
                            const float* __restrict__ wkva,
                            const float* __restrict__ wqb,
                            const float* __restrict__ wkvb,
                            const float* __restrict__ wo)
{
    __shared__ float tt[32][33];
    if (blockIdx.x < PREP_SPLIT_BLOCKS) {
        const int i = blockIdx.x * 256 + threadIdx.x;
        const float4 v = *(const float4*)&hidden[(size_t)i * 4];
        *(uint2*)&g_hid_h[(size_t)i * 4] =
            make_uint2(packh2(v.x, v.y), packh2(v.z, v.w));
        return;
    }
    const int bid = blockIdx.x - PREP_SPLIT_BLOCKS;
    const float* W; __half *Th, *Tl; int K, N, nx, t;
    if (bid < 1920)      { t = bid;        W=wqa;  Th=g_wqa_h;  Tl=g_wqa_l;  K=HIDN;    N=Q_RANK;  nx=24; }
    else if (bid < 2640) { t = bid-1920;   W=wkva; Th=g_wkva_h; Tl=g_wkva_l; K=HIDN;    N=CKV_D;   nx=9; }
    else if (bid < 5520) { t = bid-2640;   W=wqb;  Th=g_wqb_h;  Tl=g_wqb_l;  K=Q_RANK;  N=QD_ALL;  nx=120; }
    else if (bid < 6800) { t = bid-5520;   W=wkvb; Th=g_wkvb_h; Tl=g_wkvb_l; K=KV_RANK; N=KVD_ALL; nx=160; }
    else                 { t = bid-6800;   W=wo;   Th=g_wo_h;   Tl=g_wo_l;   K=HIDN;    N=OD_ALL;  nx=80; }
    const int n0 = (t % nx) * 32;
    const int k0 = (t / nx) * 32;

    const int tx = threadIdx.x & 31;
    const int ty = threadIdx.x >> 5;       // 0..7
#pragma unroll
    for (int j = 0; j < 4; j++)
        tt[ty + j * 8][tx] = W[(size_t)(k0 + ty + j * 8) * N + n0 + tx];
    __syncthreads();
#pragma unroll
    for (int j = 0; j < 4; j++) {
        const float v = tt[tx][ty + j * 8];
        __half h, l;
        splith1(v, h, l);
        const size_t o = (size_t)(n0 + ty + j * 8) * K + k0 + tx;
        Th[o] = h; Tl[o] = l;
    }
}

// ---------------------------------------------------------------------------
// Fused tensor GEMM (fp16): C = A(hi) @ [Bt(hi)(+Bt(lo))]^T
// Tile 128x128, BK=32, 3-stage cp.async pipeline, ONE barrier per chunk.
// LO=false -> single product (skips lo copy + lo mma).
// ---------------------------------------------------------------------------
struct GemmDesc {
    const __half *Ah, *Bh, *Bl;
    float* C;
    __half *Ch, *Cl;     // Cl may be null (hi-only output)
    int N, K;
};

constexpr int GST      = 40;
constexpr int G_OFF_A  = 0;
constexpr int G_OFF_BH = 128 * GST * 2;      // 10240
constexpr int G_OFF_BL = 2 * 128 * GST * 2;  // 20480
constexpr int G_STAGE  = 3 * 128 * GST * 2;  // 30720
constexpr int G_SMEM   = 3 * G_STAGE;        // 92160 (3 stages)

template<bool SPLIT_OUT, bool LO>
__global__ __launch_bounds__(256, 2)
void tgemm2_kernel(GemmDesc d0, GemmDesc d1, int xsplit)
{
    extern __shared__ char smc[];
    const uint32_t sb0 = smem_u32(smc);

    const bool second = blockIdx.x >= (unsigned)xsplit;
    const GemmDesc d = second ? d1 : d0;
    const int bx = second ? (blockIdx.x - xsplit) : blockIdx.x;
    const int N = d.N, K = d.K;

    const int tid  = threadIdx.x;
    const int warp = tid >> 5;
    const int lane = tid & 31;
    const int wr   = warp >> 1;
    const int wc   = warp & 1;
    const int row0 = blockIdx.y * 128;
    const int col0 = bx * 128;

    auto issue_chunk = [&](int ch, int st) {
        const int k0 = ch << 5;
        const uint32_t sb = sb0 + st * G_STAGE;
#pragma unroll
        for (int i = 0; i < 2; i++) {
            const int s  = tid + i * 256;
            const int r  = s >> 2;
            const int kc = (s & 3) * 8;
            const uint32_t dd = r * (GST * 2) + kc * 2;
            CP16(sb + G_OFF_A + dd, &d.Ah[(size_t)(row0 + r) * K + k0 + kc]);
            const int n = col0 + r;
            const bool pr = n < N;
            const size_t bo = (size_t)(pr ? n : 0) * K + k0 + kc;
            CP16P(sb + G_OFF_BH + dd, &d.Bh[bo], pr);
            if (LO) CP16P(sb + G_OFF_BL + dd, &d.Bl[bo], pr);
        }
    };

    float acc[2][8][4];
#pragma unroll
    for (int mf = 0; mf < 2; mf++)
#pragma unroll
        for (int nf = 0; nf < 8; nf++)
#pragma unroll
            for (int r = 0; r < 4; r++) acc[mf][nf][r] = 0.f;

    const int a_row = (lane & 15);
    const int a_col = (lane >> 4) * 8;
    const int b_row = (lane >> 4) * 8 + (lane & 7);
    const int b_col = ((lane >> 3) & 1) * 8;

    auto compute_stage = [&](int st) {
        const uint32_t Ah = sb0 + st * G_STAGE + G_OFF_A;
        const uint32_t Bh = sb0 + st * G_STAGE + G_OFF_BH;
        const uint32_t Bl = sb0 + st * G_STAGE + G_OFF_BL;
#pragma unroll
        for (int ks = 0; ks < 32; ks += 16) {
            uint32_t ah[2][4];
#pragma unroll
            for (int mf = 0; mf < 2; mf++) {
                const uint32_t off = ((wr * 32 + mf * 16 + a_row) * GST + ks + a_col) * 2;
                ldmatrix_x4(ah[mf][0], ah[mf][1], ah[mf][2], ah[mf][3], Ah + off);
            }
#pragma unroll
            for (int np = 0; np < 4; np++) {
                uint32_t bh[4], bl[4];
                const uint32_t off = ((wc * 64 + np * 16 + b_row) * GST + ks + b_col) * 2;
                ldmatrix_x4(bh[0], bh[1], bh[2], bh[3], Bh + off);
                if (LO) ldmatrix_x4(bl[0], bl[1], bl[2], bl[3], Bl + off);
#pragma unroll
                for (int mf = 0; mf < 2; mf++) {
                    mma_f16(acc[mf][np*2],   ah[mf], bh + 0);
                    mma_f16(acc[mf][np*2+1], ah[mf], bh + 2);
                    if (LO) {
                        mma_f16(acc[mf][np*2],   ah[mf], bl + 0);
                        mma_f16(acc[mf][np*2+1], ah[mf], bl + 2);
                    }
                }
            }
        }
    };

    // 3-stage pipeline, one barrier per chunk.
    const int nch = K >> 5;           // >= 8 for all our shapes
    issue_chunk(0, 0); CP_COMMIT();
    issue_chunk(1, 1); CP_COMMIT();
    for (int ch = 0; ch < nch; ch++) {
        if (ch + 1 < nch) CP_WAIT(1); else CP_WAIT(0);
        __syncthreads();              // all warps done computing stage (ch-1)%3 too
        compute_stage(ch % 3);
        if (ch + 2 < nch) {
            issue_chunk(ch + 2, (ch + 2) % 3);
            CP_COMMIT();
        }
    }

#pragma unroll
    for (int mf = 0; mf < 2; mf++) {
        const int r0 = row0 + wr * 32 + mf * 16 + (lane >> 2);
#pragma unroll
        for (int nf = 0; nf < 8; nf++) {
            const int c = col0 + wc * 64 + nf * 8 + (lane & 3) * 2;
            if (c < N) {
                if (SPLIT_OUT) {
                    if (d.Cl) {
                        uint32_t hp, lp;
                        splith2(acc[mf][nf][0], acc[mf][nf][1], hp, lp);
                        *(uint32_t*)&d.Ch[(size_t)r0 * N + c] = hp;
                        *(uint32_t*)&d.Cl[(size_t)r0 * N + c] = lp;
                        splith2(acc[mf][nf][2], acc[mf][nf][3], hp, lp);
                        *(uint32_t*)&d.Ch[(size_t)(r0 + 8) * N + c] = hp;
                        *(uint32_t*)&d.Cl[(size_t)(r0 + 8) * N + c] = lp;
                    } else {
                        *(uint32_t*)&d.Ch[(size_t)r0 * N + c] =
                            packh2(acc[mf][nf][0], acc[mf][nf][1]);
                        *(uint32_t*)&d.Ch[(size_t)(r0 + 8) * N + c] =
                            packh2(acc[mf][nf][2], acc[mf][nf][3]);
                    }
                } else {
                    *(float2*)&d.C[(size_t)r0 * N + c] =
                        make_float2(acc[mf][nf][0], acc[mf][nf][1]);
                    *(float2*)&d.C[(size_t)(r0 + 8) * N + c] =
                        make_float2(acc[mf][nf][2], acc[mf][nf][3]);
                }
            }
        }
    }
}

// ---------------------------------------------------------------------------
// Both RMSNorms in one launch -> fp16 hi plane
// ---------------------------------------------------------------------------
__global__ void rmsnorm2_kernel(const float* __restrict__ qln,
                                const float* __restrict__ kvln)
{
    const float* in; const float* w; __half* oh;
    int dim, istride, row;
    if (blockIdx.x < NTOK) {
        row = blockIdx.x;
        in = g_qa; w = qln; oh = g_qan_h;
        dim = Q_RANK; istride = Q_RANK;
    } else {
        row = blockIdx.x - NTOK;
        in = g_ckv; w = kvln; oh = g_kvn_h;
        dim = KV_RANK; istride = CKV_D;
    }
    const float* x = in + (size_t)row * istride;
    float ss = 0.f;
    for (int i = threadIdx.x; i < dim; i += blockDim.x) { float v = x[i]; ss += v * v; }
#pragma unroll
    for (int o = 16; o > 0; o >>= 1) ss += __shfl_xor_sync(0xffffffffu, ss, o);
    __shared__ float sh[8];
    __shared__ float s_inv;
    if ((threadIdx.x & 31) == 0) sh[threadIdx.x >> 5] = ss;
    __syncthreads();
    if (threadIdx.x == 0) {
        float t = 0.f;
        const int nw = blockDim.x >> 5;
        for (int i = 0; i < nw; i++) t += sh[i];
        s_inv = rsqrtf(t / (float)dim + 1e-5f);
    }
    __syncthreads();
    const float inv = s_inv;
    for (int i = threadIdx.x; i < dim; i += blockDim.x)
        oh[(size_t)row * dim + i] = __float2half_rn(x[i] * inv * w[i]);
}

// ---------------------------------------------------------------------------
// RoPE: q hi plane in-place (rope dims), ckv tail -> krot hi/lo planes
// ---------------------------------------------------------------------------
__global__ void rope_kernel(__half* __restrict__ qh,
                            const float* __restrict__ ckv,
                            __half* __restrict__ krh, __half* __restrict__ krl,
                            const float* __restrict__ cosb, const float* __restrict__ sinb)
{
    const int token = blockIdx.x;
    const int s = token & (SEQ - 1);
    for (int i = threadIdx.x; i < (NHEAD + 1) * 32; i += blockDim.x) {
        const int h = i >> 5;
        const int d = i & 31;
        const float c  = cosb[s * ROPE_D + d];
        const float sn = sinb[s * ROPE_D + d];
        if (h < NHEAD) {
            const size_t base = (size_t)token * QD_ALL + h * QK_D + NOPE_D;
            const size_t pi   = base + ((d < 16) ? d + 16 : d - 16);
            const float x  = __half2float(qh[base + d]);
            float pr = __half2float(qh[pi]);
            if (d < 16) pr = -pr;
            __syncwarp();
            qh[base + d] = __float2half_rn(x * c + pr * sn);
        } else {
            const float* kb = ckv + (size_t)token * CKV_D + KV_RANK;
            const float x  = kb[d];
            const float pr = (d < 16) ? -kb[d + 16] : kb[d - 16];
            __half hh, ll;
            splith1(x * c + pr * sn, hh, ll);
            krh[(size_t)token * ROPE_D + d] = hh;
            krl[(size_t)token * ROPE_D + d] = ll;
        }
    }
}

// ---------------------------------------------------------------------------
// Flash attention. Q hi; K hi+lo (2-product S); V hi only (1-product PV).
// BQ=128, BK=64, 256 threads, 8 warps. Largest-qt-first; K/V prefetch.
// ---------------------------------------------------------------------------
constexpr int AQ_ST = 104;
constexpr int AV_ST = 72;
constexpr int A_QT  = 128 * AQ_ST;
constexpr int A_KT  = 64 * AQ_ST;
constexpr int A_VT  = 64 * AV_ST;
constexpr int ATTN_SMEM = (A_QT + 2*A_KT + A_VT) * (int)sizeof(__half);  // 62464

__global__ __launch_bounds__(256, 2)
void attn_mma_kernel(const __half* __restrict__ qh,
                     const __half* __restrict__ kvh, const __half* __restrict__ kvl,
                     const __half* __restrict__ krh, const __half* __restrict__ krl,
                     __half* __restrict__ oh)
{
    extern __shared__ __half smh[];
    const uint32_t uQ  = smem_u32(smh);
    const uint32_t uKh = uQ  + A_QT * 2;
    const uint32_t uKl = uKh + A_KT * 2;
    const uint32_t uVh = uKl + A_KT * 2;

    const int bh = blockIdx.y;
    const int b  = bh / NHEAD;
    const int h  = bh % NHEAD;
    const int qt = (SEQ / 128 - 1) - blockIdx.x;   // largest work first
    const int q0 = qt * 128;
    const int tid  = threadIdx.x;
    const int warp = tid >> 5;
    const int lane = tid & 31;
    const int gr   = lane >> 2;
    const int qd   = lane & 3;
    const size_t tok0 = (size_t)b * SEQ;

    const int a_row = (lane & 15);
    const int a_col = (lane >> 4) * 8;
    const int b_row = (lane >> 4) * 8 + (lane & 7);
    const int b_col = ((lane >> 3) & 1) * 8;
    const int v_row = (lane & 15);
    const int v_col = (lane >> 4) * 8;

    auto issue_k = [&](int kt) {
        const int k0 = kt * 64;
#pragma unroll
        for (int i = 0; i < 3; i++) {
            const int s = tid + i * 256;
            if (s < 512) {
                const int r = s >> 3, c8 = (s & 7) * 8;
                const size_t src = (tok0 + k0 + r) * KVD_ALL + h * 128 + c8;
                CP16(uKh + (r * AQ_ST + c8) * 2, &kvh[src]);
                CP16(uKl + (r * AQ_ST + c8) * 2, &kvl[src]);
            } else {
                const int t = s - 512;
                const int r = t >> 2, c8 = 64 + (t & 3) * 8;
                const size_t src = (tok0 + k0 + r) * ROPE_D + (c8 - 64);
                CP16(uKh + (r * AQ_ST + c8) * 2, &krh[src]);
                CP16(uKl + (r * AQ_ST + c8) * 2, &krl[src]);
            }
        }
    };
    auto issue_v = [&](int kt) {
        const int k0 = kt * 64;
#pragma unroll
        for (int i = 0; i < 2; i++) {
            const int s = tid + i * 256;
            const int r = s >> 3;
            const int c8 = (s & 7) * 8;
            const size_t src = (tok0 + k0 + r) * KVD_ALL + h * 128 + 64 + c8;
            CP16(uVh + (r * AV_ST + c8) * 2, &kvh[src]);
        }
    };

    // ---- Q tile copy (128 x 96, hi plane) ----
#pragma unroll
    for (int i = 0; i < 6; i++) {
        const int s  = tid + i * 256;        // 0..1535
        const int r  = s / 12;
        const int c8 = (s - r * 12) * 8;
        CP16(uQ + (r * AQ_ST + c8) * 2, &qh[(tok0 + q0 + r) * QD_ALL + h * QK_D + c8]);
    }
    CP_COMMIT();          // group: Q
    issue_k(0);
    CP_COMMIT();          // group: K0
    issue_v(0);
    CP_COMMIT();          // group: V0

    float oacc[8][4];
#pragma unroll
    for (int nf = 0; nf < 8; nf++)
#pragma unroll
        for (int r = 0; r < 4; r++) oacc[nf][r] = 0.f;
    float mA = -1e30f, mB = -1e30f, lA = 0.f, lB = 0.f;

    const int q0w  = q0 + warp * 16;
    const int rowA = q0w + gr;
    const int rowB = rowA + 8;
    const int nkt  = 2 * qt + 2;

    for (int kt = 0; kt < nkt; kt++) {
        const int k0 = kt * 64;

        CP_WAIT(1);            // K_t (and Q) landed; V_t may be in flight
        __syncthreads();

        // ---- S = Q @ K^T (2-product) ----
        float sa[8][4];
#pragma unroll
        for (int nf = 0; nf < 8; nf++)
#pragma unroll
            for (int r = 0; r < 4; r++) sa[nf][r] = 0.f;

#pragma unroll
        for (int ks = 0; ks < 96; ks += 16) {
            uint32_t ah[4];
            const uint32_t aoff = ((warp * 16 + a_row) * AQ_ST + ks + a_col) * 2;
            ldmatrix_x4(ah[0], ah[1], ah[2], ah[3], uQ + aoff);
#pragma unroll
            for (int np = 0; np < 4; np++) {
                uint32_t bhf[4], blf[4];
                const uint32_t boff = ((np * 16 + b_row) * AQ_ST + ks + b_col) * 2;
                ldmatrix_x4(bhf[0], bhf[1], bhf[2], bhf[3], uKh + boff);
                ldmatrix_x4(blf[0], blf[1], blf[2], blf[3], uKl + boff);
                mma_f16(sa[np*2],   ah, bhf + 0);
                mma_f16(sa[np*2],   ah, blf + 0);
                mma_f16(sa[np*2+1], ah, bhf + 2);
                mma_f16(sa[np*2+1], ah, blf + 2);
            }
        }
        __syncthreads();       // all warps done reading K smem
        if (kt + 1 < nkt) issue_k(kt + 1);
        CP_COMMIT();           // group K_{t+1} (possibly empty)

        // ---- scale + mask ----
#pragma unroll
        for (int nf = 0; nf < 8; nf++)
#pragma unroll
            for (int r = 0; r < 4; r++) sa[nf][r] *= SC2;
        if (k0 + 63 > q0w) {
#pragma unroll
            for (int nf = 0; nf < 8; nf++) {
                const int col = k0 + nf * 8 + qd * 2;
                if (col     > rowA) sa[nf][0] = -1e30f;
                if (col + 1 > rowA) sa[nf][1] = -1e30f;
                if (col     > rowB) sa[nf][2] = -1e30f;
                if (col + 1 > rowB) sa[nf][3] = -1e30f;
            }
        }

        // ---- online softmax ----
        float mxA = -1e30f, mxB = -1e30f;
#pragma unroll
        for (int nf = 0; nf < 8; nf++) {
            mxA = fmaxf(mxA, fmaxf(sa[nf][0], sa[nf][1]));
            mxB = fmaxf(mxB, fmaxf(sa[nf][2], sa[nf][3]));
        }
        mxA = fmaxf(mxA, __shfl_xor_sync(0xffffffffu, mxA, 1));
        mxA = fmaxf(mxA, __shfl_xor_sync(0xffffffffu, mxA, 2));
        mxB = fmaxf(mxB, __shfl_xor_sync(0xffffffffu, mxB, 1));
        mxB = fmaxf(mxB, __shfl_xor_sync(0xffffffffu, mxB, 2));
        const float mnA = fmaxf(mA, mxA);
        const float mnB = fmaxf(mB, mxB);
        const float alA = fexp2(mA - mnA);
        const float alB = fexp2(mB - mnB);
        mA = mnA; mB = mnB;

        float rsA = 0.f, rsB = 0.f;
#pragma unroll
        for (int nf = 0; nf < 8; nf++) {
            sa[nf][0] = fexp2(sa[nf][0] - mnA); rsA += sa[nf][0];
            sa[nf][1] = fexp2(sa[nf][1] - mnA); rsA += sa[nf][1];
            sa[nf][2] = fexp2(sa[nf][2] - mnB); rsB += sa[nf][2];
            sa[nf][3] = fexp2(sa[nf][3] - mnB); rsB += sa[nf][3];
        }
        rsA += __shfl_xor_sync(0xffffffffu, rsA, 1);
        rsA += __shfl_xor_sync(0xffffffffu, rsA, 2);
        rsB += __shfl_xor_sync(0xffffffffu, rsB, 1);
        rsB += __shfl_xor_sync(0xffffffffu, rsB, 2);
        lA = lA * alA + rsA;
        lB = lB * alB + rsB;
#pragma unroll
        for (int nf = 0; nf < 8; nf++) {
            oacc[nf][0] *= alA; oacc[nf][1] *= alA;
            oacc[nf][2] *= alB; oacc[nf][3] *= alB;
        }

        CP_WAIT(1);            // V_t landed; K_{t+1} may be in flight
        __syncthreads();

        // ---- O += P @ V  (P fp16; V hi only, 1-product) ----
#pragma unroll
        for (int t = 0; t < 4; t++) {
            uint32_t ph[4];
            ph[0] = packh2(sa[2*t][0],   sa[2*t][1]);
            ph[1] = packh2(sa[2*t][2],   sa[2*t][3]);
            ph[2] = packh2(sa[2*t+1][0], sa[2*t+1][1]);
            ph[3] = packh2(sa[2*t+1][2], sa[2*t+1][3]);
#pragma unroll
            for (int np = 0; np < 4; np++) {
                uint32_t vhf[4];
                const uint32_t voff = ((t * 16 + v_row) * AV_ST + np * 16 + v_col) * 2;
                ldmatrix_x4_t(vhf[0], vhf[1], vhf[2], vhf[3], uVh + voff);
                mma_f16(oacc[np*2],   ph, vhf + 0);
                mma_f16(oacc[np*2+1], ph, vhf + 2);
            }
        }
        __syncthreads();       // all warps done reading V smem
        if (kt + 1 < nkt) issue_v(kt + 1);
        CP_COMMIT();           // group V_{t+1} (possibly empty)
    }

    // ---- finalize + write hi plane ----
    const float invA = 1.f / lA;
    const float invB = 1.f / lB;
#pragma unroll
    for (int nf = 0; nf < 8; nf++) {
        const int col = h * V_D + nf * 8 + qd * 2;
        *(uint32_t*)&oh[(tok0 + rowA) * (size_t)OD_ALL + col] =
            packh2(oacc[nf][0] * invA, oacc[nf][1] * invA);
        *(uint32_t*)&oh[(tok0 + rowB) * (size_t)OD_ALL + col] =
            packh2(oacc[nf][2] * invB, oacc[nf][3] * invB);
    }
}

// ---------------------------------------------------------------------------
// Launch
// ---------------------------------------------------------------------------
extern "C" void kernel_launch(void* const* d_in, const int* in_sizes, int n_in,
                              void* d_out, int out_size)
{
    const float* hidden = (const float*)d_in[0];
    const float* cosb   = (const float*)d_in[1];
    const float* sinb   = (const float*)d_in[2];
    const float* wq_a   = (const float*)d_in[3];
    const float* q_ln   = (const float*)d_in[4];
    const float* wq_b   = (const float*)d_in[5];
    const float* wkv_a  = (const float*)d_in[6];
    const float* kv_ln  = (const float*)d_in[7];
    const float* wkv_b  = (const float*)d_in[8];
    const float* wo     = (const float*)d_in[9];
    float* out = (float*)d_out;

    __half *hidh, *wqah, *wqal, *wkvah, *wkval, *wqbh, *wqbl,
           *wkvbh, *wkvbl, *woh, *qanh, *kvnh,
           *qhp, *kvhp, *kvlp, *krhp, *krlp, *ath;
    float *qa, *ckv;
    cudaGetSymbolAddress((void**)&hidh,  g_hid_h);
    cudaGetSymbolAddress((void**)&wqah,  g_wqa_h);  cudaGetSymbolAddress((void**)&wqal,  g_wqa_l);
    cudaGetSymbolAddress((void**)&wkvah, g_wkva_h); cudaGetSymbolAddress((void**)&wkval, g_wkva_l);
    cudaGetSymbolAddress((void**)&wqbh,  g_wqb_h);  cudaGetSymbolAddress((void**)&wqbl,  g_wqb_l);
    cudaGetSymbolAddress((void**)&wkvbh, g_wkvb_h); cudaGetSymbolAddress((void**)&wkvbl, g_wkvb_l);
    cudaGetSymbolAddress((void**)&woh,   g_wo_h);
    cudaGetSymbolAddress((void**)&qa,    g_qa);     cudaGetSymbolAddress((void**)&ckv,   g_ckv);
    cudaGetSymbolAddress((void**)&qanh,  g_qan_h);  cudaGetSymbolAddress((void**)&kvnh,  g_kvn_h);
    cudaGetSymbolAddress((void**)&qhp,   g_q_h);
    cudaGetSymbolAddress((void**)&kvhp,  g_kv_h);   cudaGetSymbolAddress((void**)&kvlp,  g_kv_l);
    cudaGetSymbolAddress((void**)&krhp,  g_kr_h);   cudaGetSymbolAddress((void**)&krlp,  g_kr_l);
    cudaGetSymbolAddress((void**)&ath,   g_at_h);

    cudaFuncSetAttribute((const void*)tgemm2_kernel<false, true>,
                         cudaFuncAttributeMaxDynamicSharedMemorySize, G_SMEM);
    cudaFuncSetAttribute((const void*)tgemm2_kernel<true, true>,
                         cudaFuncAttributeMaxDynamicSharedMemorySize, G_SMEM);
    cudaFuncSetAttribute((const void*)tgemm2_kernel<false, false>,
                         cudaFuncAttributeMaxDynamicSharedMemorySize, G_SMEM);
    cudaFuncSetAttribute((const void*)attn_mma_kernel,
                         cudaFuncAttributeMaxDynamicSharedMemorySize, ATTN_SMEM);

    const dim3 blk(256);
    const int mt = NTOK / 128;

    // 0: prep (hidden convert + all weight transpose/splits)
    prep_kernel<<<PREP_TOTAL_BLOCKS, 256>>>(hidden, wq_a, wkv_a, wq_b, wkv_b, wo);

    // 1: fused GEMM pair: qa = hid@wqa  |  ckv = hid@wkva   (fp32 out, 2-product)
    {
        GemmDesc d0 = { hidh, wqah,  wqal,  qa,  nullptr, nullptr, Q_RANK, HIDN };
        GemmDesc d1 = { hidh, wkvah, wkval, ckv, nullptr, nullptr, CKV_D,  HIDN };
        tgemm2_kernel<false, true><<<dim3(6 + 3, mt), blk, G_SMEM>>>(d0, d1, 6);
    }
    // 2: both rmsnorms -> fp16 hi planes
    rmsnorm2_kernel<<<2 * NTOK, 256>>>(q_ln, kv_ln);
    // 3: fused GEMM pair: q = qan@wqb (hi out) | kv = kvn@wkvb (hi+lo out), 2-product
    {
        GemmDesc d0 = { qanh, wqbh,  wqbl,  nullptr, qhp,  nullptr, QD_ALL,  Q_RANK };
        GemmDesc d1 = { kvnh, wkvbh, wkvbl, nullptr, kvhp, kvlp,    KVD_ALL, KV_RANK };
        tgemm2_kernel<true, true><<<dim3(30 + 40, mt), blk, G_SMEM>>>(d0, d1, 30);
    }
    // 4: rope
    rope_kernel<<<NTOK, 256>>>(qhp, ckv, krhp, krlp, cosb, sinb);
    // 5: attention (largest qt first)
    attn_mma_kernel<<<dim3(SEQ / 128, 2 * NHEAD), blk, ATTN_SMEM>>>(
        qhp, kvhp, kvlp, krhp, krlp, ath);
    // 6: out = attn @ wo   (1-product: wo hi only)
    {
        GemmDesc d0 = { ath, woh, woh, out, nullptr, nullptr, HIDN, OD_ALL };
        tgemm2_kernel<false, false><<<dim3(HIDN / 128, mt), blk, G_SMEM>>>(d0, d0, HIDN / 128);
    }
}

// round 12
// speedup vs baseline: 1.4304x; 1.4304x over previous
#include <cuda_runtime.h>
#include <cuda_fp16.h>
#include <cstdint>

// ---------------------------------------------------------------------------
// Problem constants
// ---------------------------------------------------------------------------
constexpr int SEQ    = 2048;
constexpr int HIDN   = 2560;
constexpr int NHEAD  = 40;
constexpr int NOPE_D = 64;
constexpr int ROPE_D = 32;
constexpr int QK_D   = NOPE_D + ROPE_D;    // 96
constexpr int V_D    = 64;
constexpr int Q_RANK = 768;
constexpr int KV_RANK= 256;
constexpr int CKV_D  = KV_RANK + ROPE_D;   // 288
constexpr int NTOK   = 2 * SEQ;            // 4096
constexpr int QD_ALL = NHEAD * QK_D;       // 3840
constexpr int KVD_ALL= NHEAD * (NOPE_D + V_D); // 5120
constexpr int OD_ALL = NHEAD * V_D;        // 2560
constexpr float SCALE = 0.10206207261596577f;
constexpr float SC2   = SCALE * 1.4426950408889634f;

// ---------------------------------------------------------------------------
// Scratch. Activations: fp16 hi only. Weights & K: hi+lo. V/wo: hi only.
// ---------------------------------------------------------------------------
__device__ __half g_hid_h [NTOK * HIDN];
__device__ __half g_wqa_h [Q_RANK * HIDN];     // transposed [N][K]
__device__ __half g_wqa_l [Q_RANK * HIDN];
__device__ __half g_wkva_h[CKV_D * HIDN];
__device__ __half g_wkva_l[CKV_D * HIDN];
__device__ __half g_wqb_h [QD_ALL * Q_RANK];
__device__ __half g_wqb_l [QD_ALL * Q_RANK];
__device__ __half g_wkvb_h[KVD_ALL * KV_RANK];
__device__ __half g_wkvb_l[KVD_ALL * KV_RANK];
__device__ __half g_wo_h  [HIDN * OD_ALL];
__device__ __half g_wo_l  [HIDN * OD_ALL];     // produced by prep, unused (kept for simplicity)
__device__ float  g_qa    [NTOK * Q_RANK];
__device__ float  g_ckv   [NTOK * CKV_D];
__device__ __half g_qan_h [NTOK * Q_RANK];
__device__ __half g_kvn_h [NTOK * KV_RANK];
__device__ __half g_q_h   [NTOK * QD_ALL];
__device__ __half g_kv_h  [NTOK * KVD_ALL];
__device__ __half g_kv_l  [NTOK * KVD_ALL];
__device__ __half g_kr_h  [NTOK * ROPE_D];
__device__ __half g_kr_l  [NTOK * ROPE_D];
__device__ __half g_at_h  [NTOK * OD_ALL];

// ---------------------------------------------------------------------------
// PTX helpers (portable sm_80+ subset)
// ---------------------------------------------------------------------------
__device__ __forceinline__ uint32_t smem_u32(const void* p) {
    uint32_t a;
    asm("{ .reg .u64 t; cvta.to.shared.u64 t, %1; cvt.u32.u64 %0, t; }"
        : "=r"(a) : "l"(p));
    return a;
}
__device__ __forceinline__ void ldmatrix_x4(uint32_t& r0, uint32_t& r1,
                                            uint32_t& r2, uint32_t& r3, uint32_t addr) {
    asm volatile("ldmatrix.sync.aligned.m8n8.x4.shared.b16 {%0,%1,%2,%3}, [%4];"
                 : "=r"(r0), "=r"(r1), "=r"(r2), "=r"(r3) : "r"(addr));
}
__device__ __forceinline__ void ldmatrix_x4_t(uint32_t& r0, uint32_t& r1,
                                              uint32_t& r2, uint32_t& r3, uint32_t addr) {
    asm volatile("ldmatrix.sync.aligned.m8n8.x4.trans.shared.b16 {%0,%1,%2,%3}, [%4];"
                 : "=r"(r0), "=r"(r1), "=r"(r2), "=r"(r3) : "r"(addr));
}
__device__ __forceinline__ void mma_f16(float* c, const uint32_t* a, const uint32_t* b) {
    asm volatile(
        "mma.sync.aligned.m16n8k16.row.col.f32.f16.f16.f32 "
        "{%0,%1,%2,%3}, {%4,%5,%6,%7}, {%8,%9}, {%0,%1,%2,%3};"
        : "+f"(c[0]), "+f"(c[1]), "+f"(c[2]), "+f"(c[3])
        : "r"(a[0]), "r"(a[1]), "r"(a[2]), "r"(a[3]), "r"(b[0]), "r"(b[1]));
}
#define CP16(dst, src) \
    asm volatile("cp.async.cg.shared.global [%0], [%1], 16;" :: "r"(dst), "l"(src))
#define CP16P(dst, src, pred) \
    asm volatile("cp.async.cg.shared.global [%0], [%1], 16, %2;" \
                 :: "r"(dst), "l"(src), "r"((pred) ? 16 : 0))
#define CP_COMMIT() asm volatile("cp.async.commit_group;" ::: "memory")
#define CP_WAIT(n)  asm volatile("cp.async.wait_group %0;" :: "n"(n) : "memory")

__device__ __forceinline__ uint32_t packh2(float x0, float x1) {
    uint32_t p;
    asm("cvt.rn.f16x2.f32 %0, %1, %2;" : "=r"(p) : "f"(x1), "f"(x0));
    return p;
}
__device__ __forceinline__ void splith1(float x, __half& h, __half& l) {
    h = __float2half_rn(x);
    l = __float2half_rn(x - __half2float(h));
}
__device__ __forceinline__ void splith2(float x0, float x1, uint32_t& hp, uint32_t& lp) {
    const __half h0 = __float2half_rn(x0), h1 = __float2half_rn(x1);
    hp = ((uint32_t)__half_as_ushort(h1) << 16) | (uint32_t)__half_as_ushort(h0);
    lp = packh2(x0 - __half2float(h0), x1 - __half2float(h1));
}
__device__ __forceinline__ float fexp2(float x) {
    float r;
    asm("ex2.approx.ftz.f32 %0, %1;" : "=f"(r) : "f"(x));
    return r;
}

// ---------------------------------------------------------------------------
// Prep: hidden fp32->fp16 + all weight transpose+splits, one launch
// ---------------------------------------------------------------------------
constexpr int PREP_SPLIT_BLOCKS = NTOK * HIDN / 4 / 256;  // 10240
constexpr int PREP_TOTAL_BLOCKS = PREP_SPLIT_BLOCKS + 13200;

__global__ void prep_kernel(const float* __restrict__ hidden,
                            const float* __restrict__ wqa,
                            const float* __restrict__ wkva,
                            const float* __restrict__ wqb,
                            const float* __restrict__ wkvb,
                            const float* __restrict__ wo)
{
    __shared__ float tt[32][33];
    if (blockIdx.x < PREP_SPLIT_BLOCKS) {
        const int i = blockIdx.x * 256 + threadIdx.x;
        const float4 v = *(const float4*)&hidden[(size_t)i * 4];
        *(uint2*)&g_hid_h[(size_t)i * 4] =
            make_uint2(packh2(v.x, v.y), packh2(v.z, v.w));
        return;
    }
    const int bid = blockIdx.x - PREP_SPLIT_BLOCKS;
    const float* W; __half *Th, *Tl; int K, N, nx, t;
    if (bid < 1920)      { t = bid;        W=wqa;  Th=g_wqa_h;  Tl=g_wqa_l;  K=HIDN;    N=Q_RANK;  nx=24; }
    else if (bid < 2640) { t = bid-1920;   W=wkva; Th=g_wkva_h; Tl=g_wkva_l; K=HIDN;    N=CKV_D;   nx=9; }
    else if (bid < 5520) { t = bid-2640;   W=wqb;  Th=g_wqb_h;  Tl=g_wqb_l;  K=Q_RANK;  N=QD_ALL;  nx=120; }
    else if (bid < 6800) { t = bid-5520;   W=wkvb; Th=g_wkvb_h; Tl=g_wkvb_l; K=KV_RANK; N=KVD_ALL; nx=160; }
    else                 { t = bid-6800;   W=wo;   Th=g_wo_h;   Tl=g_wo_l;   K=HIDN;    N=OD_ALL;  nx=80; }
    const int n0 = (t % nx) * 32;
    const int k0 = (t / nx) * 32;

    const int tx = threadIdx.x & 31;
    const int ty = threadIdx.x >> 5;       // 0..7
#pragma unroll
    for (int j = 0; j < 4; j++)
        tt[ty + j * 8][tx] = W[(size_t)(k0 + ty + j * 8) * N + n0 + tx];
    __syncthreads();
#pragma unroll
    for (int j = 0; j < 4; j++) {
        const float v = tt[tx][ty + j * 8];
        __half h, l;
        splith1(v, h, l);
        const size_t o = (size_t)(n0 + ty + j * 8) * K + k0 + tx;
        Th[o] = h; Tl[o] = l;
    }
}

// ---------------------------------------------------------------------------
// Fused tensor GEMM (fp16): C = A(hi) @ [Bt(hi)(+Bt(lo))]^T
// Tile 128x128, BK=32, 2-stage cp.async pipeline (Round-9 proven structure).
// LO=false -> single product (skips lo copy + lo mma).
// ---------------------------------------------------------------------------
struct GemmDesc {
    const __half *Ah, *Bh, *Bl;
    float* C;
    __half *Ch, *Cl;     // Cl may be null (hi-only output)
    int N, K;
};

constexpr int GST      = 40;
constexpr int G_OFF_A  = 0;
constexpr int G_OFF_BH = 128 * GST * 2;      // 10240
constexpr int G_OFF_BL = 2 * 128 * GST * 2;  // 20480
constexpr int G_STAGE  = 3 * 128 * GST * 2;  // 30720
constexpr int G_SMEM   = 2 * G_STAGE;        // 61440 (2 stages)

template<bool SPLIT_OUT, bool LO>
__global__ __launch_bounds__(256, 2)
void tgemm2_kernel(GemmDesc d0, GemmDesc d1, int xsplit)
{
    extern __shared__ char smc[];
    const uint32_t sb0 = smem_u32(smc);

    const bool second = blockIdx.x >= (unsigned)xsplit;
    const GemmDesc d = second ? d1 : d0;
    const int bx = second ? (blockIdx.x - xsplit) : blockIdx.x;
    const int N = d.N, K = d.K;

    const int tid  = threadIdx.x;
    const int warp = tid >> 5;
    const int lane = tid & 31;
    const int wr   = warp >> 1;
    const int wc   = warp & 1;
    const int row0 = blockIdx.y * 128;
    const int col0 = bx * 128;

    auto issue_chunk = [&](int ch, int st) {
        const int k0 = ch << 5;
        const uint32_t sb = sb0 + st * G_STAGE;
#pragma unroll
        for (int i = 0; i < 2; i++) {
            const int s  = tid + i * 256;
            const int r  = s >> 2;
            const int kc = (s & 3) * 8;
            const uint32_t dd = r * (GST * 2) + kc * 2;
            CP16(sb + G_OFF_A + dd, &d.Ah[(size_t)(row0 + r) * K + k0 + kc]);
            const int n = col0 + r;
            const bool pr = n < N;
            const size_t bo = (size_t)(pr ? n : 0) * K + k0 + kc;
            CP16P(sb + G_OFF_BH + dd, &d.Bh[bo], pr);
            if (LO) CP16P(sb + G_OFF_BL + dd, &d.Bl[bo], pr);
        }
    };

    float acc[2][8][4];
#pragma unroll
    for (int mf = 0; mf < 2; mf++)
#pragma unroll
        for (int nf = 0; nf < 8; nf++)
#pragma unroll
            for (int r = 0; r < 4; r++) acc[mf][nf][r] = 0.f;

    const int a_row = (lane & 15);
    const int a_col = (lane >> 4) * 8;
    const int b_row = (lane >> 4) * 8 + (lane & 7);
    const int b_col = ((lane >> 3) & 1) * 8;

    auto compute_stage = [&](int st) {
        const uint32_t Ah = sb0 + st * G_STAGE + G_OFF_A;
        const uint32_t Bh = sb0 + st * G_STAGE + G_OFF_BH;
        const uint32_t Bl = sb0 + st * G_STAGE + G_OFF_BL;
#pragma unroll
        for (int ks = 0; ks < 32; ks += 16) {
            uint32_t ah[2][4];
#pragma unroll
            for (int mf = 0; mf < 2; mf++) {
                const uint32_t off = ((wr * 32 + mf * 16 + a_row) * GST + ks + a_col) * 2;
                ldmatrix_x4(ah[mf][0], ah[mf][1], ah[mf][2], ah[mf][3], Ah + off);
            }
#pragma unroll
            for (int np = 0; np < 4; np++) {
                uint32_t bh[4], bl[4];
                const uint32_t off = ((wc * 64 + np * 16 + b_row) * GST + ks + b_col) * 2;
                ldmatrix_x4(bh[0], bh[1], bh[2], bh[3], Bh + off);
                if (LO) ldmatrix_x4(bl[0], bl[1], bl[2], bl[3], Bl + off);
#pragma unroll
                for (int mf = 0; mf < 2; mf++) {
                    mma_f16(acc[mf][np*2],   ah[mf], bh + 0);
                    mma_f16(acc[mf][np*2+1], ah[mf], bh + 2);
                    if (LO) {
                        mma_f16(acc[mf][np*2],   ah[mf], bl + 0);
                        mma_f16(acc[mf][np*2+1], ah[mf], bl + 2);
                    }
                }
            }
        }
    };

    // 2-stage pipeline (proven): issue ch+1, wait ch, barrier, compute, barrier.
    const int nch = K >> 5;
    issue_chunk(0, 0);
    CP_COMMIT();
    for (int ch = 0; ch < nch; ch++) {
        if (ch + 1 < nch) {
            issue_chunk(ch + 1, (ch + 1) & 1);
            CP_COMMIT();
            CP_WAIT(1);
        } else {
            CP_WAIT(0);
        }
        __syncthreads();
        compute_stage(ch & 1);
        __syncthreads();
    }

#pragma unroll
    for (int mf = 0; mf < 2; mf++) {
        const int r0 = row0 + wr * 32 + mf * 16 + (lane >> 2);
#pragma unroll
        for (int nf = 0; nf < 8; nf++) {
            const int c = col0 + wc * 64 + nf * 8 + (lane & 3) * 2;
            if (c < N) {
                if (SPLIT_OUT) {
                    if (d.Cl) {
                        uint32_t hp, lp;
                        splith2(acc[mf][nf][0], acc[mf][nf][1], hp, lp);
                        *(uint32_t*)&d.Ch[(size_t)r0 * N + c] = hp;
                        *(uint32_t*)&d.Cl[(size_t)r0 * N + c] = lp;
                        splith2(acc[mf][nf][2], acc[mf][nf][3], hp, lp);
                        *(uint32_t*)&d.Ch[(size_t)(r0 + 8) * N + c] = hp;
                        *(uint32_t*)&d.Cl[(size_t)(r0 + 8) * N + c] = lp;
                    } else {
                        *(uint32_t*)&d.Ch[(size_t)r0 * N + c] =
                            packh2(acc[mf][nf][0], acc[mf][nf][1]);
                        *(uint32_t*)&d.Ch[(size_t)(r0 + 8) * N + c] =
                            packh2(acc[mf][nf][2], acc[mf][nf][3]);
                    }
                } else {
                    *(float2*)&d.C[(size_t)r0 * N + c] =
                        make_float2(acc[mf][nf][0], acc[mf][nf][1]);
                    *(float2*)&d.C[(size_t)(r0 + 8) * N + c] =
                        make_float2(acc[mf][nf][2], acc[mf][nf][3]);
                }
            }
        }
    }
}

// ---------------------------------------------------------------------------
// Both RMSNorms in one launch -> fp16 hi plane
// ---------------------------------------------------------------------------
__global__ void rmsnorm2_kernel(const float* __restrict__ qln,
                                const float* __restrict__ kvln)
{
    const float* in; const float* w; __half* oh;
    int dim, istride, row;
    if (blockIdx.x < NTOK) {
        row = blockIdx.x;
        in = g_qa; w = qln; oh = g_qan_h;
        dim = Q_RANK; istride = Q_RANK;
    } else {
        row = blockIdx.x - NTOK;
        in = g_ckv; w = kvln; oh = g_kvn_h;
        dim = KV_RANK; istride = CKV_D;
    }
    const float* x = in + (size_t)row * istride;
    float ss = 0.f;
    for (int i = threadIdx.x; i < dim; i += blockDim.x) { float v = x[i]; ss += v * v; }
#pragma unroll
    for (int o = 16; o > 0; o >>= 1) ss += __shfl_xor_sync(0xffffffffu, ss, o);
    __shared__ float sh[8];
    __shared__ float s_inv;
    if ((threadIdx.x & 31) == 0) sh[threadIdx.x >> 5] = ss;
    __syncthreads();
    if (threadIdx.x == 0) {
        float t = 0.f;
        const int nw = blockDim.x >> 5;
        for (int i = 0; i < nw; i++) t += sh[i];
        s_inv = rsqrtf(t / (float)dim + 1e-5f);
    }
    __syncthreads();
    const float inv = s_inv;
    for (int i = threadIdx.x; i < dim; i += blockDim.x)
        oh[(size_t)row * dim + i] = __float2half_rn(x[i] * inv * w[i]);
}

// ---------------------------------------------------------------------------
// RoPE: q hi plane in-place (rope dims), ckv tail -> krot hi/lo planes
// ---------------------------------------------------------------------------
__global__ void rope_kernel(__half* __restrict__ qh,
                            const float* __restrict__ ckv,
                            __half* __restrict__ krh, __half* __restrict__ krl,
                            const float* __restrict__ cosb, const float* __restrict__ sinb)
{
    const int token = blockIdx.x;
    const int s = token & (SEQ - 1);
    for (int i = threadIdx.x; i < (NHEAD + 1) * 32; i += blockDim.x) {
        const int h = i >> 5;
        const int d = i & 31;
        const float c  = cosb[s * ROPE_D + d];
        const float sn = sinb[s * ROPE_D + d];
        if (h < NHEAD) {
            const size_t base = (size_t)token * QD_ALL + h * QK_D + NOPE_D;
            const size_t pi   = base + ((d < 16) ? d + 16 : d - 16);
            const float x  = __half2float(qh[base + d]);
            float pr = __half2float(qh[pi]);
            if (d < 16) pr = -pr;
            __syncwarp();
            qh[base + d] = __float2half_rn(x * c + pr * sn);
        } else {
            const float* kb = ckv + (size_t)token * CKV_D + KV_RANK;
            const float x  = kb[d];
            const float pr = (d < 16) ? -kb[d + 16] : kb[d - 16];
            __half hh, ll;
            splith1(x * c + pr * sn, hh, ll);
            krh[(size_t)token * ROPE_D + d] = hh;
            krl[(size_t)token * ROPE_D + d] = ll;
        }
    }
}

// ---------------------------------------------------------------------------
// Flash attention. Q hi; K hi+lo (2-product S); V hi only (1-product PV).
// BQ=128, BK=64, 256 threads, 8 warps. Largest-qt-first; K/V prefetch.
// ---------------------------------------------------------------------------
constexpr int AQ_ST = 104;
constexpr int AV_ST = 72;
constexpr int A_QT  = 128 * AQ_ST;
constexpr int A_KT  = 64 * AQ_ST;
constexpr int A_VT  = 64 * AV_ST;
constexpr int ATTN_SMEM = (A_QT + 2*A_KT + A_VT) * (int)sizeof(__half);  // 62464

__global__ __launch_bounds__(256, 2)
void attn_mma_kernel(const __half* __restrict__ qh,
                     const __half* __restrict__ kvh, const __half* __restrict__ kvl,
                     const __half* __restrict__ krh, const __half* __restrict__ krl,
                     __half* __restrict__ oh)
{
    extern __shared__ __half smh[];
    const uint32_t uQ  = smem_u32(smh);
    const uint32_t uKh = uQ  + A_QT * 2;
    const uint32_t uKl = uKh + A_KT * 2;
    const uint32_t uVh = uKl + A_KT * 2;

    const int bh = blockIdx.y;
    const int b  = bh / NHEAD;
    const int h  = bh % NHEAD;
    const int qt = (SEQ / 128 - 1) - blockIdx.x;   // largest work first
    const int q0 = qt * 128;
    const int tid  = threadIdx.x;
    const int warp = tid >> 5;
    const int lane = tid & 31;
    const int gr   = lane >> 2;
    const int qd   = lane & 3;
    const size_t tok0 = (size_t)b * SEQ;

    const int a_row = (lane & 15);
    const int a_col = (lane >> 4) * 8;
    const int b_row = (lane >> 4) * 8 + (lane & 7);
    const int b_col = ((lane >> 3) & 1) * 8;
    const int v_row = (lane & 15);
    const int v_col = (lane >> 4) * 8;

    auto issue_k = [&](int kt) {
        const int k0 = kt * 64;
#pragma unroll
        for (int i = 0; i < 3; i++) {
            const int s = tid + i * 256;
            if (s < 512) {
                const int r = s >> 3, c8 = (s & 7) * 8;
                const size_t src = (tok0 + k0 + r) * KVD_ALL + h * 128 + c8;
                CP16(uKh + (r * AQ_ST + c8) * 2, &kvh[src]);
                CP16(uKl + (r * AQ_ST + c8) * 2, &kvl[src]);
            } else {
                const int t = s - 512;
                const int r = t >> 2, c8 = 64 + (t & 3) * 8;
                const size_t src = (tok0 + k0 + r) * ROPE_D + (c8 - 64);
                CP16(uKh + (r * AQ_ST + c8) * 2, &krh[src]);
                CP16(uKl + (r * AQ_ST + c8) * 2, &krl[src]);
            }
        }
    };
    auto issue_v = [&](int kt) {
        const int k0 = kt * 64;
#pragma unroll
        for (int i = 0; i < 2; i++) {
            const int ss = tid + i * 256;    // 0..511
            const int r = ss >> 3;
            const int c8 = (ss & 7) * 8;
            const size_t src = (tok0 + k0 + r) * KVD_ALL + h * 128 + 64 + c8;
            CP16(uVh + (r * AV_ST + c8) * 2, &kvh[src]);
        }
    };

    // ---- Q tile copy (128 x 96, hi plane) ----
#pragma unroll
    for (int i = 0; i < 6; i++) {
        const int s  = tid + i * 256;        // 0..1535
        const int r  = s / 12;
        const int c8 = (s - r * 12) * 8;
        CP16(uQ + (r * AQ_ST + c8) * 2, &qh[(tok0 + q0 + r) * QD_ALL + h * QK_D + c8]);
    }
    CP_COMMIT();          // group: Q
    issue_k(0);
    CP_COMMIT();          // group: K0
    issue_v(0);
    CP_COMMIT();          // group: V0

    float oacc[8][4];
#pragma unroll
    for (int nf = 0; nf < 8; nf++)
#pragma unroll
        for (int r = 0; r < 4; r++) oacc[nf][r] = 0.f;
    float mA = -1e30f, mB = -1e30f, lA = 0.f, lB = 0.f;

    const int q0w  = q0 + warp * 16;
    const int rowA = q0w + gr;
    const int rowB = rowA + 8;
    const int nkt  = 2 * qt + 2;

    for (int kt = 0; kt < nkt; kt++) {
        const int k0 = kt * 64;

        CP_WAIT(1);            // K_t (and Q) landed; V_t may be in flight
        __syncthreads();

        // ---- S = Q @ K^T (2-product) ----
        float sa[8][4];
#pragma unroll
        for (int nf = 0; nf < 8; nf++)
#pragma unroll
            for (int r = 0; r < 4; r++) sa[nf][r] = 0.f;

#pragma unroll
        for (int ks = 0; ks < 96; ks += 16) {
            uint32_t ah[4];
            const uint32_t aoff = ((warp * 16 + a_row) * AQ_ST + ks + a_col) * 2;
            ldmatrix_x4(ah[0], ah[1], ah[2], ah[3], uQ + aoff);
#pragma unroll
            for (int np = 0; np < 4; np++) {
                uint32_t bhf[4], blf[4];
                const uint32_t boff = ((np * 16 + b_row) * AQ_ST + ks + b_col) * 2;
                ldmatrix_x4(bhf[0], bhf[1], bhf[2], bhf[3], uKh + boff);
                ldmatrix_x4(blf[0], blf[1], blf[2], blf[3], uKl + boff);
                mma_f16(sa[np*2],   ah, bhf + 0);
                mma_f16(sa[np*2],   ah, blf + 0);
                mma_f16(sa[np*2+1], ah, bhf + 2);
                mma_f16(sa[np*2+1], ah, blf + 2);
            }
        }
        __syncthreads();       // all warps done reading K smem
        if (kt + 1 < nkt) issue_k(kt + 1);
        CP_COMMIT();           // group K_{t+1} (possibly empty)

        // ---- scale + mask ----
#pragma unroll
        for (int nf = 0; nf < 8; nf++)
#pragma unroll
            for (int r = 0; r < 4; r++) sa[nf][r] *= SC2;
        if (k0 + 63 > q0w) {
#pragma unroll
            for (int nf = 0; nf < 8; nf++) {
                const int col = k0 + nf * 8 + qd * 2;
                if (col     > rowA) sa[nf][0] = -1e30f;
                if (col + 1 > rowA) sa[nf][1] = -1e30f;
                if (col     > rowB) sa[nf][2] = -1e30f;
                if (col + 1 > rowB) sa[nf][3] = -1e30f;
            }
        }

        // ---- online softmax ----
        float mxA = -1e30f, mxB = -1e30f;
#pragma unroll
        for (int nf = 0; nf < 8; nf++) {
            mxA = fmaxf(mxA, fmaxf(sa[nf][0], sa[nf][1]));
            mxB = fmaxf(mxB, fmaxf(sa[nf][2], sa[nf][3]));
        }
        mxA = fmaxf(mxA, __shfl_xor_sync(0xffffffffu, mxA, 1));
        mxA = fmaxf(mxA, __shfl_xor_sync(0xffffffffu, mxA, 2));
        mxB = fmaxf(mxB, __shfl_xor_sync(0xffffffffu, mxB, 1));
        mxB = fmaxf(mxB, __shfl_xor_sync(0xffffffffu, mxB, 2));
        const float mnA = fmaxf(mA, mxA);
        const float mnB = fmaxf(mB, mxB);
        const float alA = fexp2(mA - mnA);
        const float alB = fexp2(mB - mnB);
        mA = mnA; mB = mnB;

        float rsA = 0.f, rsB = 0.f;
#pragma unroll
        for (int nf = 0; nf < 8; nf++) {
            sa[nf][0] = fexp2(sa[nf][0] - mnA); rsA += sa[nf][0];
            sa[nf][1] = fexp2(sa[nf][1] - mnA); rsA += sa[nf][1];
            sa[nf][2] = fexp2(sa[nf][2] - mnB); rsB += sa[nf][2];
            sa[nf][3] = fexp2(sa[nf][3] - mnB); rsB += sa[nf][3];
        }
        rsA += __shfl_xor_sync(0xffffffffu, rsA, 1);
        rsA += __shfl_xor_sync(0xffffffffu, rsA, 2);
        rsB += __shfl_xor_sync(0xffffffffu, rsB, 1);
        rsB += __shfl_xor_sync(0xffffffffu, rsB, 2);
        lA = lA * alA + rsA;
        lB = lB * alB + rsB;
#pragma unroll
        for (int nf = 0; nf < 8; nf++) {
            oacc[nf][0] *= alA; oacc[nf][1] *= alA;
            oacc[nf][2] *= alB; oacc[nf][3] *= alB;
        }

        CP_WAIT(1);            // V_t landed; K_{t+1} may be in flight
        __syncthreads();

        // ---- O += P @ V  (P fp16; V hi only, 1-product) ----
#pragma unroll
        for (int t = 0; t < 4; t++) {
            uint32_t ph[4];
            ph[0] = packh2(sa[2*t][0],   sa[2*t][1]);
            ph[1] = packh2(sa[2*t][2],   sa[2*t][3]);
            ph[2] = packh2(sa[2*t+1][0], sa[2*t+1][1]);
            ph[3] = packh2(sa[2*t+1][2], sa[2*t+1][3]);
#pragma unroll
            for (int np = 0; np < 4; np++) {
                uint32_t vhf[4];
                const uint32_t voff = ((t * 16 + v_row) * AV_ST + np * 16 + v_col) * 2;
                ldmatrix_x4_t(vhf[0], vhf[1], vhf[2], vhf[3], uVh + voff);
                mma_f16(oacc[np*2],   ph, vhf + 0);
                mma_f16(oacc[np*2+1], ph, vhf + 2);
            }
        }
        __syncthreads();       // all warps done reading V smem
        if (kt + 1 < nkt) issue_v(kt + 1);
        CP_COMMIT();           // group V_{t+1} (possibly empty)
    }

    // ---- finalize + write hi plane ----
    const float invA = 1.f / lA;
    const float invB = 1.f / lB;
#pragma unroll
    for (int nf = 0; nf < 8; nf++) {
        const int col = h * V_D + nf * 8 + qd * 2;
        *(uint32_t*)&oh[(tok0 + rowA) * (size_t)OD_ALL + col] =
            packh2(oacc[nf][0] * invA, oacc[nf][1] * invA);
        *(uint32_t*)&oh[(tok0 + rowB) * (size_t)OD_ALL + col] =
            packh2(oacc[nf][2] * invB, oacc[nf][3] * invB);
    }
}

// ---------------------------------------------------------------------------
// Launch
// ---------------------------------------------------------------------------
extern "C" void kernel_launch(void* const* d_in, const int* in_sizes, int n_in,
                              void* d_out, int out_size)
{
    const float* hidden = (const float*)d_in[0];
    const float* cosb   = (const float*)d_in[1];
    const float* sinb   = (const float*)d_in[2];
    const float* wq_a   = (const float*)d_in[3];
    const float* q_ln   = (const float*)d_in[4];
    const float* wq_b   = (const float*)d_in[5];
    const float* wkv_a  = (const float*)d_in[6];
    const float* kv_ln  = (const float*)d_in[7];
    const float* wkv_b  = (const float*)d_in[8];
    const float* wo     = (const float*)d_in[9];
    float* out = (float*)d_out;

    __half *hidh, *wqah, *wqal, *wkvah, *wkval, *wqbh, *wqbl,
           *wkvbh, *wkvbl, *woh, *qanh, *kvnh,
           *qhp, *kvhp, *kvlp, *krhp, *krlp, *ath;
    float *qa, *ckv;
    cudaGetSymbolAddress((void**)&hidh,  g_hid_h);
    cudaGetSymbolAddress((void**)&wqah,  g_wqa_h);  cudaGetSymbolAddress((void**)&wqal,  g_wqa_l);
    cudaGetSymbolAddress((void**)&wkvah, g_wkva_h); cudaGetSymbolAddress((void**)&wkval, g_wkva_l);
    cudaGetSymbolAddress((void**)&wqbh,  g_wqb_h);  cudaGetSymbolAddress((void**)&wqbl,  g_wqb_l);
    cudaGetSymbolAddress((void**)&wkvbh, g_wkvb_h); cudaGetSymbolAddress((void**)&wkvbl, g_wkvb_l);
    cudaGetSymbolAddress((void**)&woh,   g_wo_h);
    cudaGetSymbolAddress((void**)&qa,    g_qa);     cudaGetSymbolAddress((void**)&ckv,   g_ckv);
    cudaGetSymbolAddress((void**)&qanh,  g_qan_h);  cudaGetSymbolAddress((void**)&kvnh,  g_kvn_h);
    cudaGetSymbolAddress((void**)&qhp,   g_q_h);
    cudaGetSymbolAddress((void**)&kvhp,  g_kv_h);   cudaGetSymbolAddress((void**)&kvlp,  g_kv_l);
    cudaGetSymbolAddress((void**)&krhp,  g_kr_h);   cudaGetSymbolAddress((void**)&krlp,  g_kr_l);
    cudaGetSymbolAddress((void**)&ath,   g_at_h);

    cudaFuncSetAttribute((const void*)tgemm2_kernel<false, true>,
                         cudaFuncAttributeMaxDynamicSharedMemorySize, G_SMEM);
    cudaFuncSetAttribute((const void*)tgemm2_kernel<true, true>,
                         cudaFuncAttributeMaxDynamicSharedMemorySize, G_SMEM);
    cudaFuncSetAttribute((const void*)tgemm2_kernel<false, false>,
                         cudaFuncAttributeMaxDynamicSharedMemorySize, G_SMEM);
    cudaFuncSetAttribute((const void*)attn_mma_kernel,
                         cudaFuncAttributeMaxDynamicSharedMemorySize, ATTN_SMEM);

    const dim3 blk(256);
    const int mt = NTOK / 128;

    // 0: prep (hidden convert + all weight transpose/splits)
    prep_kernel<<<PREP_TOTAL_BLOCKS, 256>>>(hidden, wq_a, wkv_a, wq_b, wkv_b, wo);

    // 1: fused GEMM pair: qa = hid@wqa  |  ckv = hid@wkva   (fp32 out, 2-product)
    {
        GemmDesc d0 = { hidh, wqah,  wqal,  qa,  nullptr, nullptr, Q_RANK, HIDN };
        GemmDesc d1 = { hidh, wkvah, wkval, ckv, nullptr, nullptr, CKV_D,  HIDN };
        tgemm2_kernel<false, true><<<dim3(6 + 3, mt), blk, G_SMEM>>>(d0, d1, 6);
    }
    // 2: both rmsnorms -> fp16 hi planes
    rmsnorm2_kernel<<<2 * NTOK, 256>>>(q_ln, kv_ln);
    // 3: fused GEMM pair: q = qan@wqb (hi out) | kv = kvn@wkvb (hi+lo out), 2-product
    {
        GemmDesc d0 = { qanh, wqbh,  wqbl,  nullptr, qhp,  nullptr, QD_ALL,  Q_RANK };
        GemmDesc d1 = { kvnh, wkvbh, wkvbl, nullptr, kvhp, kvlp,    KVD_ALL, KV_RANK };
        tgemm2_kernel<true, true><<<dim3(30 + 40, mt), blk, G_SMEM>>>(d0, d1, 30);
    }
    // 4: rope
    rope_kernel<<<NTOK, 256>>>(qhp, ckv, krhp, krlp, cosb, sinb);
    // 5: attention (largest qt first)
    attn_mma_kernel<<<dim3(SEQ / 128, 2 * NHEAD), blk, ATTN_SMEM>>>(
        qhp, kvhp, kvlp, krhp, krlp, ath);
    // 6: out = attn @ wo   (1-product: wo hi only)
    {
        GemmDesc d0 = { ath, woh, woh, out, nullptr, nullptr, HIDN, OD_ALL };
        tgemm2_kernel<false, false><<<dim3(HIDN / 128, mt), blk, G_SMEM>>>(d0, d0, HIDN / 128);
    }
}

// round 13
// speedup vs baseline: 1.5963x; 1.1159x over previous
#include <cuda_runtime.h>
#include <cuda_fp16.h>
#include <cstdint>

// ---------------------------------------------------------------------------
// Problem constants
// ---------------------------------------------------------------------------
constexpr int SEQ    = 2048;
constexpr int HIDN   = 2560;
constexpr int NHEAD  = 40;
constexpr int NOPE_D = 64;
constexpr int ROPE_D = 32;
constexpr int QK_D   = NOPE_D + ROPE_D;    // 96
constexpr int V_D    = 64;
constexpr int Q_RANK = 768;
constexpr int KV_RANK= 256;
constexpr int CKV_D  = KV_RANK + ROPE_D;   // 288
constexpr int NTOK   = 2 * SEQ;            // 4096
constexpr int QD_ALL = NHEAD * QK_D;       // 3840
constexpr int KVD_ALL= NHEAD * (NOPE_D + V_D); // 5120
constexpr int OD_ALL = NHEAD * V_D;        // 2560
constexpr float SCALE = 0.10206207261596577f;
constexpr float SC2   = SCALE * 1.4426950408889634f;

// ---------------------------------------------------------------------------
// Scratch. Activations / K / V / wo: fp16 hi only. GEMM weights: hi+lo.
// ---------------------------------------------------------------------------
__device__ __half g_hid_h [NTOK * HIDN];
__device__ __half g_wqa_h [Q_RANK * HIDN];     // transposed [N][K]
__device__ __half g_wqa_l [Q_RANK * HIDN];
__device__ __half g_wkva_h[CKV_D * HIDN];
__device__ __half g_wkva_l[CKV_D * HIDN];
__device__ __half g_wqb_h [QD_ALL * Q_RANK];
__device__ __half g_wqb_l [QD_ALL * Q_RANK];
__device__ __half g_wkvb_h[KVD_ALL * KV_RANK];
__device__ __half g_wkvb_l[KVD_ALL * KV_RANK];
__device__ __half g_wo_h  [HIDN * OD_ALL];
__device__ float  g_qa    [NTOK * Q_RANK];
__device__ float  g_ckv   [NTOK * CKV_D];
__device__ __half g_qan_h [NTOK * Q_RANK];
__device__ __half g_kvn_h [NTOK * KV_RANK];
__device__ __half g_q_h   [NTOK * QD_ALL];
__device__ __half g_kv_h  [NTOK * KVD_ALL];
__device__ __half g_kr_h  [NTOK * ROPE_D];
__device__ __half g_at_h  [NTOK * OD_ALL];

// ---------------------------------------------------------------------------
// PTX helpers (portable sm_80+ subset)
// ---------------------------------------------------------------------------
__device__ __forceinline__ uint32_t smem_u32(const void* p) {
    uint32_t a;
    asm("{ .reg .u64 t; cvta.to.shared.u64 t, %1; cvt.u32.u64 %0, t; }"
        : "=r"(a) : "l"(p));
    return a;
}
__device__ __forceinline__ void ldmatrix_x4(uint32_t& r0, uint32_t& r1,
                                            uint32_t& r2, uint32_t& r3, uint32_t addr) {
    asm volatile("ldmatrix.sync.aligned.m8n8.x4.shared.b16 {%0,%1,%2,%3}, [%4];"
                 : "=r"(r0), "=r"(r1), "=r"(r2), "=r"(r3) : "r"(addr));
}
__device__ __forceinline__ void ldmatrix_x4_t(uint32_t& r0, uint32_t& r1,
                                              uint32_t& r2, uint32_t& r3, uint32_t addr) {
    asm volatile("ldmatrix.sync.aligned.m8n8.x4.trans.shared.b16 {%0,%1,%2,%3}, [%4];"
                 : "=r"(r0), "=r"(r1), "=r"(r2), "=r"(r3) : "r"(addr));
}
__device__ __forceinline__ void mma_f16(float* c, const uint32_t* a, const uint32_t* b) {
    asm volatile(
        "mma.sync.aligned.m16n8k16.row.col.f32.f16.f16.f32 "
        "{%0,%1,%2,%3}, {%4,%5,%6,%7}, {%8,%9}, {%0,%1,%2,%3};"
        : "+f"(c[0]), "+f"(c[1]), "+f"(c[2]), "+f"(c[3])
        : "r"(a[0]), "r"(a[1]), "r"(a[2]), "r"(a[3]), "r"(b[0]), "r"(b[1]));
}
#define CP16(dst, src) \
    asm volatile("cp.async.cg.shared.global [%0], [%1], 16;" :: "r"(dst), "l"(src))
#define CP16P(dst, src, pred) \
    asm volatile("cp.async.cg.shared.global [%0], [%1], 16, %2;" \
                 :: "r"(dst), "l"(src), "r"((pred) ? 16 : 0))
#define CP_COMMIT() asm volatile("cp.async.commit_group;" ::: "memory")
#define CP_WAIT(n)  asm volatile("cp.async.wait_group %0;" :: "n"(n) : "memory")

__device__ __forceinline__ uint32_t packh2(float x0, float x1) {
    uint32_t p;
    asm("cvt.rn.f16x2.f32 %0, %1, %2;" : "=r"(p) : "f"(x1), "f"(x0));
    return p;
}
__device__ __forceinline__ void splith1(float x, __half& h, __half& l) {
    h = __float2half_rn(x);
    l = __float2half_rn(x - __half2float(h));
}
__device__ __forceinline__ void splith2(float x0, float x1, uint32_t& hp, uint32_t& lp) {
    const __half h0 = __float2half_rn(x0), h1 = __float2half_rn(x1);
    hp = ((uint32_t)__half_as_ushort(h1) << 16) | (uint32_t)__half_as_ushort(h0);
    lp = packh2(x0 - __half2float(h0), x1 - __half2float(h1));
}
__device__ __forceinline__ float fexp2(float x) {
    float r;
    asm("ex2.approx.ftz.f32 %0, %1;" : "=f"(r) : "f"(x));
    return r;
}

// ---------------------------------------------------------------------------
// Prep: hidden fp32->fp16 + all weight transpose+splits, one launch
// (wo: hi plane only — lo never consumed)
// ---------------------------------------------------------------------------
constexpr int PREP_SPLIT_BLOCKS = NTOK * HIDN / 4 / 256;  // 10240
constexpr int PREP_TOTAL_BLOCKS = PREP_SPLIT_BLOCKS + 13200;

__global__ void prep_kernel(const float* __restrict__ hidden,
                            const float* __restrict__ wqa,
                            const float* __restrict__ wkva,
                            const float* __restrict__ wqb,
                            const float* __restrict__ wkvb,
                            const float* __restrict__ wo)
{
    __shared__ float tt[32][33];
    if (blockIdx.x < PREP_SPLIT_BLOCKS) {
        const int i = blockIdx.x * 256 + threadIdx.x;
        const float4 v = *(const float4*)&hidden[(size_t)i * 4];
        *(uint2*)&g_hid_h[(size_t)i * 4] =
            make_uint2(packh2(v.x, v.y), packh2(v.z, v.w));
        return;
    }
    const int bid = blockIdx.x - PREP_SPLIT_BLOCKS;
    const float* W; __half *Th, *Tl; int K, N, nx, t;
    if (bid < 1920)      { t = bid;        W=wqa;  Th=g_wqa_h;  Tl=g_wqa_l;  K=HIDN;    N=Q_RANK;  nx=24; }
    else if (bid < 2640) { t = bid-1920;   W=wkva; Th=g_wkva_h; Tl=g_wkva_l; K=HIDN;    N=CKV_D;   nx=9; }
    else if (bid < 5520) { t = bid-2640;   W=wqb;  Th=g_wqb_h;  Tl=g_wqb_l;  K=Q_RANK;  N=QD_ALL;  nx=120; }
    else if (bid < 6800) { t = bid-5520;   W=wkvb; Th=g_wkvb_h; Tl=g_wkvb_l; K=KV_RANK; N=KVD_ALL; nx=160; }
    else                 { t = bid-6800;   W=wo;   Th=g_wo_h;   Tl=nullptr;  K=HIDN;    N=OD_ALL;  nx=80; }
    const int n0 = (t % nx) * 32;
    const int k0 = (t / nx) * 32;

    const int tx = threadIdx.x & 31;
    const int ty = threadIdx.x >> 5;       // 0..7
#pragma unroll
    for (int j = 0; j < 4; j++)
        tt[ty + j * 8][tx] = W[(size_t)(k0 + ty + j * 8) * N + n0 + tx];
    __syncthreads();
#pragma unroll
    for (int j = 0; j < 4; j++) {
        const float v = tt[tx][ty + j * 8];
        __half h, l;
        splith1(v, h, l);
        const size_t o = (size_t)(n0 + ty + j * 8) * K + k0 + tx;
        Th[o] = h;
        if (Tl) Tl[o] = l;
    }
}

// ---------------------------------------------------------------------------
// Fused tensor GEMM (fp16): C = A(hi) @ [Bt(hi)(+Bt(lo))]^T
// Tile 128x128, BK=32, 2-stage cp.async pipeline (proven structure).
// LO=false -> single product (skips lo copy + lo mma).
// ---------------------------------------------------------------------------
struct GemmDesc {
    const __half *Ah, *Bh, *Bl;
    float* C;
    __half *Ch, *Cl;     // Cl may be null (hi-only output)
    int N, K;
};

constexpr int GST      = 40;
constexpr int G_OFF_A  = 0;
constexpr int G_OFF_BH = 128 * GST * 2;      // 10240
constexpr int G_OFF_BL = 2 * 128 * GST * 2;  // 20480
constexpr int G_STAGE  = 3 * 128 * GST * 2;  // 30720
constexpr int G_SMEM   = 2 * G_STAGE;        // 61440 (2 stages)

template<bool SPLIT_OUT, bool LO>
__global__ __launch_bounds__(256, 2)
void tgemm2_kernel(GemmDesc d0, GemmDesc d1, int xsplit)
{
    extern __shared__ char smc[];
    const uint32_t sb0 = smem_u32(smc);

    const bool second = blockIdx.x >= (unsigned)xsplit;
    const GemmDesc d = second ? d1 : d0;
    const int bx = second ? (blockIdx.x - xsplit) : blockIdx.x;
    const int N = d.N, K = d.K;

    const int tid  = threadIdx.x;
    const int warp = tid >> 5;
    const int lane = tid & 31;
    const int wr   = warp >> 1;
    const int wc   = warp & 1;
    const int row0 = blockIdx.y * 128;
    const int col0 = bx * 128;

    auto issue_chunk = [&](int ch, int st) {
        const int k0 = ch << 5;
        const uint32_t sb = sb0 + st * G_STAGE;
#pragma unroll
        for (int i = 0; i < 2; i++) {
            const int s  = tid + i * 256;
            const int r  = s >> 2;
            const int kc = (s & 3) * 8;
            const uint32_t dd = r * (GST * 2) + kc * 2;
            CP16(sb + G_OFF_A + dd, &d.Ah[(size_t)(row0 + r) * K + k0 + kc]);
            const int n = col0 + r;
            const bool pr = n < N;
            const size_t bo = (size_t)(pr ? n : 0) * K + k0 + kc;
            CP16P(sb + G_OFF_BH + dd, &d.Bh[bo], pr);
            if (LO) CP16P(sb + G_OFF_BL + dd, &d.Bl[bo], pr);
        }
    };

    float acc[2][8][4];
#pragma unroll
    for (int mf = 0; mf < 2; mf++)
#pragma unroll
        for (int nf = 0; nf < 8; nf++)
#pragma unroll
            for (int r = 0; r < 4; r++) acc[mf][nf][r] = 0.f;

    const int a_row = (lane & 15);
    const int a_col = (lane >> 4) * 8;
    const int b_row = (lane >> 4) * 8 + (lane & 7);
    const int b_col = ((lane >> 3) & 1) * 8;

    auto compute_stage = [&](int st) {
        const uint32_t Ah = sb0 + st * G_STAGE + G_OFF_A;
        const uint32_t Bh = sb0 + st * G_STAGE + G_OFF_BH;
        const uint32_t Bl = sb0 + st * G_STAGE + G_OFF_BL;
#pragma unroll
        for (int ks = 0; ks < 32; ks += 16) {
            uint32_t ah[2][4];
#pragma unroll
            for (int mf = 0; mf < 2; mf++) {
                const uint32_t off = ((wr * 32 + mf * 16 + a_row) * GST + ks + a_col) * 2;
                ldmatrix_x4(ah[mf][0], ah[mf][1], ah[mf][2], ah[mf][3], Ah + off);
            }
#pragma unroll
            for (int np = 0; np < 4; np++) {
                uint32_t bh[4], bl[4];
                const uint32_t off = ((wc * 64 + np * 16 + b_row) * GST + ks + b_col) * 2;
                ldmatrix_x4(bh[0], bh[1], bh[2], bh[3], Bh + off);
                if (LO) ldmatrix_x4(bl[0], bl[1], bl[2], bl[3], Bl + off);
#pragma unroll
                for (int mf = 0; mf < 2; mf++) {
                    mma_f16(acc[mf][np*2],   ah[mf], bh + 0);
                    mma_f16(acc[mf][np*2+1], ah[mf], bh + 2);
                    if (LO) {
                        mma_f16(acc[mf][np*2],   ah[mf], bl + 0);
                        mma_f16(acc[mf][np*2+1], ah[mf], bl + 2);
                    }
                }
            }
        }
    };

    const int nch = K >> 5;
    issue_chunk(0, 0);
    CP_COMMIT();
    for (int ch = 0; ch < nch; ch++) {
        if (ch + 1 < nch) {
            issue_chunk(ch + 1, (ch + 1) & 1);
            CP_COMMIT();
            CP_WAIT(1);
        } else {
            CP_WAIT(0);
        }
        __syncthreads();
        compute_stage(ch & 1);
        __syncthreads();
    }

#pragma unroll
    for (int mf = 0; mf < 2; mf++) {
        const int r0 = row0 + wr * 32 + mf * 16 + (lane >> 2);
#pragma unroll
        for (int nf = 0; nf < 8; nf++) {
            const int c = col0 + wc * 64 + nf * 8 + (lane & 3) * 2;
            if (c < N) {
                if (SPLIT_OUT) {
                    if (d.Cl) {
                        uint32_t hp, lp;
                        splith2(acc[mf][nf][0], acc[mf][nf][1], hp, lp);
                        *(uint32_t*)&d.Ch[(size_t)r0 * N + c] = hp;
                        *(uint32_t*)&d.Cl[(size_t)r0 * N + c] = lp;
                        splith2(acc[mf][nf][2], acc[mf][nf][3], hp, lp);
                        *(uint32_t*)&d.Ch[(size_t)(r0 + 8) * N + c] = hp;
                        *(uint32_t*)&d.Cl[(size_t)(r0 + 8) * N + c] = lp;
                    } else {
                        *(uint32_t*)&d.Ch[(size_t)r0 * N + c] =
                            packh2(acc[mf][nf][0], acc[mf][nf][1]);
                        *(uint32_t*)&d.Ch[(size_t)(r0 + 8) * N + c] =
                            packh2(acc[mf][nf][2], acc[mf][nf][3]);
                    }
                } else {
                    *(float2*)&d.C[(size_t)r0 * N + c] =
                        make_float2(acc[mf][nf][0], acc[mf][nf][1]);
                    *(float2*)&d.C[(size_t)(r0 + 8) * N + c] =
                        make_float2(acc[mf][nf][2], acc[mf][nf][3]);
                }
            }
        }
    }
}

// ---------------------------------------------------------------------------
// Both RMSNorms in one launch -> fp16 hi plane
// ---------------------------------------------------------------------------
__global__ void rmsnorm2_kernel(const float* __restrict__ qln,
                                const float* __restrict__ kvln)
{
    const float* in; const float* w; __half* oh;
    int dim, istride, row;
    if (blockIdx.x < NTOK) {
        row = blockIdx.x;
        in = g_qa; w = qln; oh = g_qan_h;
        dim = Q_RANK; istride = Q_RANK;
    } else {
        row = blockIdx.x - NTOK;
        in = g_ckv; w = kvln; oh = g_kvn_h;
        dim = KV_RANK; istride = CKV_D;
    }
    const float* x = in + (size_t)row * istride;
    float ss = 0.f;
    for (int i = threadIdx.x; i < dim; i += blockDim.x) { float v = x[i]; ss += v * v; }
#pragma unroll
    for (int o = 16; o > 0; o >>= 1) ss += __shfl_xor_sync(0xffffffffu, ss, o);
    __shared__ float sh[8];
    __shared__ float s_inv;
    if ((threadIdx.x & 31) == 0) sh[threadIdx.x >> 5] = ss;
    __syncthreads();
    if (threadIdx.x == 0) {
        float t = 0.f;
        const int nw = blockDim.x >> 5;
        for (int i = 0; i < nw; i++) t += sh[i];
        s_inv = rsqrtf(t / (float)dim + 1e-5f);
    }
    __syncthreads();
    const float inv = s_inv;
    for (int i = threadIdx.x; i < dim; i += blockDim.x)
        oh[(size_t)row * dim + i] = __float2half_rn(x[i] * inv * w[i]);
}

// ---------------------------------------------------------------------------
// RoPE: q hi plane in-place (rope dims), ckv tail -> krot hi plane
// ---------------------------------------------------------------------------
__global__ void rope_kernel(__half* __restrict__ qh,
                            const float* __restrict__ ckv,
                            __half* __restrict__ krh,
                            const float* __restrict__ cosb, const float* __restrict__ sinb)
{
    const int token = blockIdx.x;
    const int s = token & (SEQ - 1);
    for (int i = threadIdx.x; i < (NHEAD + 1) * 32; i += blockDim.x) {
        const int h = i >> 5;
        const int d = i & 31;
        const float c  = cosb[s * ROPE_D + d];
        const float sn = sinb[s * ROPE_D + d];
        if (h < NHEAD) {
            const size_t base = (size_t)token * QD_ALL + h * QK_D + NOPE_D;
            const size_t pi   = base + ((d < 16) ? d + 16 : d - 16);
            const float x  = __half2float(qh[base + d]);
            float pr = __half2float(qh[pi]);
            if (d < 16) pr = -pr;
            __syncwarp();
            qh[base + d] = __float2half_rn(x * c + pr * sn);
        } else {
            const float* kb = ckv + (size_t)token * CKV_D + KV_RANK;
            const float x  = kb[d];
            const float pr = (d < 16) ? -kb[d + 16] : kb[d - 16];
            krh[(size_t)token * ROPE_D + d] = __float2half_rn(x * c + pr * sn);
        }
    }
}

// ---------------------------------------------------------------------------
// Flash attention, all-fp16 operands (1-product S and PV).
// BQ=128, BK=64, 256 threads, 8 warps. Largest-qt-first; K/V prefetch.
// ---------------------------------------------------------------------------
constexpr int AQ_ST = 104;
constexpr int AV_ST = 72;
constexpr int A_QT  = 128 * AQ_ST;
constexpr int A_KT  = 64 * AQ_ST;
constexpr int A_VT  = 64 * AV_ST;
constexpr int ATTN_SMEM = (A_QT + A_KT + A_VT) * (int)sizeof(__half);  // 49152

__global__ __launch_bounds__(256, 2)
void attn_mma_kernel(const __half* __restrict__ qh,
                     const __half* __restrict__ kvh,
                     const __half* __restrict__ krh,
                     __half* __restrict__ oh)
{
    extern __shared__ __half smh[];
    const uint32_t uQ  = smem_u32(smh);
    const uint32_t uKh = uQ  + A_QT * 2;
    const uint32_t uVh = uKh + A_KT * 2;

    const int bh = blockIdx.y;
    const int b  = bh / NHEAD;
    const int h  = bh % NHEAD;
    const int qt = (SEQ / 128 - 1) - blockIdx.x;   // largest work first
    const int q0 = qt * 128;
    const int tid  = threadIdx.x;
    const int warp = tid >> 5;
    const int lane = tid & 31;
    const int gr   = lane >> 2;
    const int qd   = lane & 3;
    const size_t tok0 = (size_t)b * SEQ;

    const int a_row = (lane & 15);
    const int a_col = (lane >> 4) * 8;
    const int b_row = (lane >> 4) * 8 + (lane & 7);
    const int b_col = ((lane >> 3) & 1) * 8;
    const int v_row = (lane & 15);
    const int v_col = (lane >> 4) * 8;

    auto issue_k = [&](int kt) {
        const int k0 = kt * 64;
#pragma unroll
        for (int i = 0; i < 3; i++) {
            const int s = tid + i * 256;       // 0..767 chunks of 8 halfs
            if (s < 512) {
                const int r = s >> 3, c8 = (s & 7) * 8;
                const size_t src = (tok0 + k0 + r) * KVD_ALL + h * 128 + c8;
                CP16(uKh + (r * AQ_ST + c8) * 2, &kvh[src]);
            } else {
                const int t = s - 512;
                const int r = t >> 2, c8 = 64 + (t & 3) * 8;
                const size_t src = (tok0 + k0 + r) * ROPE_D + (c8 - 64);
                CP16(uKh + (r * AQ_ST + c8) * 2, &krh[src]);
            }
        }
    };
    auto issue_v = [&](int kt) {
        const int k0 = kt * 64;
#pragma unroll
        for (int i = 0; i < 2; i++) {
            const int ss = tid + i * 256;      // 0..511
            const int r = ss >> 3;
            const int c8 = (ss & 7) * 8;
            const size_t src = (tok0 + k0 + r) * KVD_ALL + h * 128 + 64 + c8;
            CP16(uVh + (r * AV_ST + c8) * 2, &kvh[src]);
        }
    };

    // ---- Q tile copy (128 x 96, hi plane) ----
#pragma unroll
    for (int i = 0; i < 6; i++) {
        const int s  = tid + i * 256;        // 0..1535
        const int r  = s / 12;
        const int c8 = (s - r * 12) * 8;
        CP16(uQ + (r * AQ_ST + c8) * 2, &qh[(tok0 + q0 + r) * QD_ALL + h * QK_D + c8]);
    }
    CP_COMMIT();          // group: Q
    issue_k(0);
    CP_COMMIT();          // group: K0
    issue_v(0);
    CP_COMMIT();          // group: V0

    float oacc[8][4];
#pragma unroll
    for (int nf = 0; nf < 8; nf++)
#pragma unroll
        for (int r = 0; r < 4; r++) oacc[nf][r] = 0.f;
    float mA = -1e30f, mB = -1e30f, lA = 0.f, lB = 0.f;

    const int q0w  = q0 + warp * 16;
    const int rowA = q0w + gr;
    const int rowB = rowA + 8;
    const int nkt  = 2 * qt + 2;

    for (int kt = 0; kt < nkt; kt++) {
        const int k0 = kt * 64;

        CP_WAIT(1);            // K_t (and Q) landed; V_t may be in flight
        __syncthreads();

        // ---- S = Q @ K^T (1-product) ----
        float sa[8][4];
#pragma unroll
        for (int nf = 0; nf < 8; nf++)
#pragma unroll
            for (int r = 0; r < 4; r++) sa[nf][r] = 0.f;

#pragma unroll
        for (int ks = 0; ks < 96; ks += 16) {
            uint32_t ah[4];
            const uint32_t aoff = ((warp * 16 + a_row) * AQ_ST + ks + a_col) * 2;
            ldmatrix_x4(ah[0], ah[1], ah[2], ah[3], uQ + aoff);
#pragma unroll
            for (int np = 0; np < 4; np++) {
                uint32_t bhf[4];
                const uint32_t boff = ((np * 16 + b_row) * AQ_ST + ks + b_col) * 2;
                ldmatrix_x4(bhf[0], bhf[1], bhf[2], bhf[3], uKh + boff);
                mma_f16(sa[np*2],   ah, bhf + 0);
                mma_f16(sa[np*2+1], ah, bhf + 2);
            }
        }
        __syncthreads();       // all warps done reading K smem
        if (kt + 1 < nkt) issue_k(kt + 1);
        CP_COMMIT();           // group K_{t+1} (possibly empty)

        // ---- scale + mask ----
#pragma unroll
        for (int nf = 0; nf < 8; nf++)
#pragma unroll
            for (int r = 0; r < 4; r++) sa[nf][r] *= SC2;
        if (k0 + 63 > q0w) {
#pragma unroll
            for (int nf = 0; nf < 8; nf++) {
                const int col = k0 + nf * 8 + qd * 2;
                if (col     > rowA) sa[nf][0] = -1e30f;
                if (col + 1 > rowA) sa[nf][1] = -1e30f;
                if (col     > rowB) sa[nf][2] = -1e30f;
                if (col + 1 > rowB) sa[nf][3] = -1e30f;
            }
        }

        // ---- online softmax ----
        float mxA = -1e30f, mxB = -1e30f;
#pragma unroll
        for (int nf = 0; nf < 8; nf++) {
            mxA = fmaxf(mxA, fmaxf(sa[nf][0], sa[nf][1]));
            mxB = fmaxf(mxB, fmaxf(sa[nf][2], sa[nf][3]));
        }
        mxA = fmaxf(mxA, __shfl_xor_sync(0xffffffffu, mxA, 1));
        mxA = fmaxf(mxA, __shfl_xor_sync(0xffffffffu, mxA, 2));
        mxB = fmaxf(mxB, __shfl_xor_sync(0xffffffffu, mxB, 1));
        mxB = fmaxf(mxB, __shfl_xor_sync(0xffffffffu, mxB, 2));
        const float mnA = fmaxf(mA, mxA);
        const float mnB = fmaxf(mB, mxB);
        const float alA = fexp2(mA - mnA);
        const float alB = fexp2(mB - mnB);
        mA = mnA; mB = mnB;

        float rsA = 0.f, rsB = 0.f;
#pragma unroll
        for (int nf = 0; nf < 8; nf++) {
            sa[nf][0] = fexp2(sa[nf][0] - mnA); rsA += sa[nf][0];
            sa[nf][1] = fexp2(sa[nf][1] - mnA); rsA += sa[nf][1];
            sa[nf][2] = fexp2(sa[nf][2] - mnB); rsB += sa[nf][2];
            sa[nf][3] = fexp2(sa[nf][3] - mnB); rsB += sa[nf][3];
        }
        rsA += __shfl_xor_sync(0xffffffffu, rsA, 1);
        rsA += __shfl_xor_sync(0xffffffffu, rsA, 2);
        rsB += __shfl_xor_sync(0xffffffffu, rsB, 1);
        rsB += __shfl_xor_sync(0xffffffffu, rsB, 2);
        lA = lA * alA + rsA;
        lB = lB * alB + rsB;
#pragma unroll
        for (int nf = 0; nf < 8; nf++) {
            oacc[nf][0] *= alA; oacc[nf][1] *= alA;
            oacc[nf][2] *= alB; oacc[nf][3] *= alB;
        }

        CP_WAIT(1);            // V_t landed; K_{t+1} may be in flight
        __syncthreads();

        // ---- O += P @ V  (1-product) ----
#pragma unroll
        for (int t = 0; t < 4; t++) {
            uint32_t ph[4];
            ph[0] = packh2(sa[2*t][0],   sa[2*t][1]);
            ph[1] = packh2(sa[2*t][2],   sa[2*t][3]);
            ph[2] = packh2(sa[2*t+1][0], sa[2*t+1][1]);
            ph[3] = packh2(sa[2*t+1][2], sa[2*t+1][3]);
#pragma unroll
            for (int np = 0; np < 4; np++) {
                uint32_t vhf[4];
                const uint32_t voff = ((t * 16 + v_row) * AV_ST + np * 16 + v_col) * 2;
                ldmatrix_x4_t(vhf[0], vhf[1], vhf[2], vhf[3], uVh + voff);
                mma_f16(oacc[np*2],   ph, vhf + 0);
                mma_f16(oacc[np*2+1], ph, vhf + 2);
            }
        }
        __syncthreads();       // all warps done reading V smem
        if (kt + 1 < nkt) issue_v(kt + 1);
        CP_COMMIT();           // group V_{t+1} (possibly empty)
    }

    // ---- finalize + write hi plane ----
    const float invA = 1.f / lA;
    const float invB = 1.f / lB;
#pragma unroll
    for (int nf = 0; nf < 8; nf++) {
        const int col = h * V_D + nf * 8 + qd * 2;
        *(uint32_t*)&oh[(tok0 + rowA) * (size_t)OD_ALL + col] =
            packh2(oacc[nf][0] * invA, oacc[nf][1] * invA);
        *(uint32_t*)&oh[(tok0 + rowB) * (size_t)OD_ALL + col] =
            packh2(oacc[nf][2] * invB, oacc[nf][3] * invB);
    }
}

// ---------------------------------------------------------------------------
// Launch
// ---------------------------------------------------------------------------
extern "C" void kernel_launch(void* const* d_in, const int* in_sizes, int n_in,
                              void* d_out, int out_size)
{
    const float* hidden = (const float*)d_in[0];
    const float* cosb   = (const float*)d_in[1];
    const float* sinb   = (const float*)d_in[2];
    const float* wq_a   = (const float*)d_in[3];
    const float* q_ln   = (const float*)d_in[4];
    const float* wq_b   = (const float*)d_in[5];
    const float* wkv_a  = (const float*)d_in[6];
    const float* kv_ln  = (const float*)d_in[7];
    const float* wkv_b  = (const float*)d_in[8];
    const float* wo     = (const float*)d_in[9];
    float* out = (float*)d_out;

    __half *hidh, *wqah, *wqal, *wkvah, *wkval, *wqbh, *wqbl,
           *wkvbh, *wkvbl, *woh, *qanh, *kvnh,
           *qhp, *kvhp, *krhp, *ath;
    float *qa, *ckv;
    cudaGetSymbolAddress((void**)&hidh,  g_hid_h);
    cudaGetSymbolAddress((void**)&wqah,  g_wqa_h);  cudaGetSymbolAddress((void**)&wqal,  g_wqa_l);
    cudaGetSymbolAddress((void**)&wkvah, g_wkva_h); cudaGetSymbolAddress((void**)&wkval, g_wkva_l);
    cudaGetSymbolAddress((void**)&wqbh,  g_wqb_h);  cudaGetSymbolAddress((void**)&wqbl,  g_wqb_l);
    cudaGetSymbolAddress((void**)&wkvbh, g_wkvb_h); cudaGetSymbolAddress((void**)&wkvbl, g_wkvb_l);
    cudaGetSymbolAddress((void**)&woh,   g_wo_h);
    cudaGetSymbolAddress((void**)&qa,    g_qa);     cudaGetSymbolAddress((void**)&ckv,   g_ckv);
    cudaGetSymbolAddress((void**)&qanh,  g_qan_h);  cudaGetSymbolAddress((void**)&kvnh,  g_kvn_h);
    cudaGetSymbolAddress((void**)&qhp,   g_q_h);
    cudaGetSymbolAddress((void**)&kvhp,  g_kv_h);
    cudaGetSymbolAddress((void**)&krhp,  g_kr_h);
    cudaGetSymbolAddress((void**)&ath,   g_at_h);

    cudaFuncSetAttribute((const void*)tgemm2_kernel<false, true>,
                         cudaFuncAttributeMaxDynamicSharedMemorySize, G_SMEM);
    cudaFuncSetAttribute((const void*)tgemm2_kernel<true, true>,
                         cudaFuncAttributeMaxDynamicSharedMemorySize, G_SMEM);
    cudaFuncSetAttribute((const void*)tgemm2_kernel<false, false>,
                         cudaFuncAttributeMaxDynamicSharedMemorySize, G_SMEM);
    cudaFuncSetAttribute((const void*)attn_mma_kernel,
                         cudaFuncAttributeMaxDynamicSharedMemorySize, ATTN_SMEM);

    const dim3 blk(256);
    const int mt = NTOK / 128;

    // 0: prep (hidden convert + all weight transpose/splits)
    prep_kernel<<<PREP_TOTAL_BLOCKS, 256>>>(hidden, wq_a, wkv_a, wq_b, wkv_b, wo);

    // 1: fused GEMM pair: qa = hid@wqa  |  ckv = hid@wkva   (fp32 out, 2-product)
    {
        GemmDesc d0 = { hidh, wqah,  wqal,  qa,  nullptr, nullptr, Q_RANK, HIDN };
        GemmDesc d1 = { hidh, wkvah, wkval, ckv, nullptr, nullptr, CKV_D,  HIDN };
        tgemm2_kernel<false, true><<<dim3(6 + 3, mt), blk, G_SMEM>>>(d0, d1, 6);
    }
    // 2: both rmsnorms -> fp16 hi planes
    rmsnorm2_kernel<<<2 * NTOK, 256>>>(q_ln, kv_ln);
    // 3: fused GEMM pair: q = qan@wqb | kv = kvn@wkvb  (hi-only outs, 2-product)
    {
        GemmDesc d0 = { qanh, wqbh,  wqbl,  nullptr, qhp,  nullptr, QD_ALL,  Q_RANK };
        GemmDesc d1 = { kvnh, wkvbh, wkvbl, nullptr, kvhp, nullptr, KVD_ALL, KV_RANK };
        tgemm2_kernel<true, true><<<dim3(30 + 40, mt), blk, G_SMEM>>>(d0, d1, 30);
    }
    // 4: rope
    rope_kernel<<<NTOK, 256>>>(qhp, ckv, krhp, cosb, sinb);
    // 5: attention (largest qt first, all-fp16 1-product)
    attn_mma_kernel<<<dim3(SEQ / 128, 2 * NHEAD), blk, ATTN_SMEM>>>(
        qhp, kvhp, krhp, ath);
    // 6: out = attn @ wo   (1-product: wo hi only)
    {
        GemmDesc d0 = { ath, woh, woh, out, nullptr, nullptr, HIDN, OD_ALL };
        tgemm2_kernel<false, false><<<dim3(HIDN / 128, mt), blk, G_SMEM>>>(d0, d0, HIDN / 128);
    }
}

// round 14
// speedup vs baseline: 1.9415x; 1.2163x over previous
#include <cuda_runtime.h>
#include <cuda_fp16.h>
#include <cstdint>

// ---------------------------------------------------------------------------
// Problem constants
// ---------------------------------------------------------------------------
constexpr int SEQ    = 2048;
constexpr int HIDN   = 2560;
constexpr int NHEAD  = 40;
constexpr int NOPE_D = 64;
constexpr int ROPE_D = 32;
constexpr int QK_D   = NOPE_D + ROPE_D;    // 96
constexpr int V_D    = 64;
constexpr int Q_RANK = 768;
constexpr int KV_RANK= 256;
constexpr int CKV_D  = KV_RANK + ROPE_D;   // 288
constexpr int NTOK   = 2 * SEQ;            // 4096
constexpr int QD_ALL = NHEAD * QK_D;       // 3840
constexpr int KVD_ALL= NHEAD * (NOPE_D + V_D); // 5120
constexpr int OD_ALL = NHEAD * V_D;        // 2560
constexpr float SCALE = 0.10206207261596577f;
constexpr float SC2   = SCALE * 1.4426950408889634f;

// ---------------------------------------------------------------------------
// Scratch. Everything fp16 hi-plane only (pure fp16 pipeline, fp32 accum).
// ---------------------------------------------------------------------------
__device__ __half g_hid_h [NTOK * HIDN];
__device__ __half g_wqa_h [Q_RANK * HIDN];     // transposed [N][K]
__device__ __half g_wkva_h[CKV_D * HIDN];
__device__ __half g_wqb_h [QD_ALL * Q_RANK];
__device__ __half g_wkvb_h[KVD_ALL * KV_RANK];
__device__ __half g_wo_h  [HIDN * OD_ALL];
__device__ float  g_qa    [NTOK * Q_RANK];
__device__ float  g_ckv   [NTOK * CKV_D];
__device__ __half g_qan_h [NTOK * Q_RANK];
__device__ __half g_kvn_h [NTOK * KV_RANK];
__device__ __half g_q_h   [NTOK * QD_ALL];
__device__ __half g_kv_h  [NTOK * KVD_ALL];
__device__ __half g_kr_h  [NTOK * ROPE_D];
__device__ __half g_at_h  [NTOK * OD_ALL];

// ---------------------------------------------------------------------------
// PTX helpers (portable sm_80+ subset)
// ---------------------------------------------------------------------------
__device__ __forceinline__ uint32_t smem_u32(const void* p) {
    uint32_t a;
    asm("{ .reg .u64 t; cvta.to.shared.u64 t, %1; cvt.u32.u64 %0, t; }"
        : "=r"(a) : "l"(p));
    return a;
}
__device__ __forceinline__ void ldmatrix_x4(uint32_t& r0, uint32_t& r1,
                                            uint32_t& r2, uint32_t& r3, uint32_t addr) {
    asm volatile("ldmatrix.sync.aligned.m8n8.x4.shared.b16 {%0,%1,%2,%3}, [%4];"
                 : "=r"(r0), "=r"(r1), "=r"(r2), "=r"(r3) : "r"(addr));
}
__device__ __forceinline__ void ldmatrix_x4_t(uint32_t& r0, uint32_t& r1,
                                              uint32_t& r2, uint32_t& r3, uint32_t addr) {
    asm volatile("ldmatrix.sync.aligned.m8n8.x4.trans.shared.b16 {%0,%1,%2,%3}, [%4];"
                 : "=r"(r0), "=r"(r1), "=r"(r2), "=r"(r3) : "r"(addr));
}
__device__ __forceinline__ void mma_f16(float* c, const uint32_t* a, const uint32_t* b) {
    asm volatile(
        "mma.sync.aligned.m16n8k16.row.col.f32.f16.f16.f32 "
        "{%0,%1,%2,%3}, {%4,%5,%6,%7}, {%8,%9}, {%0,%1,%2,%3};"
        : "+f"(c[0]), "+f"(c[1]), "+f"(c[2]), "+f"(c[3])
        : "r"(a[0]), "r"(a[1]), "r"(a[2]), "r"(a[3]), "r"(b[0]), "r"(b[1]));
}
#define CP16(dst, src) \
    asm volatile("cp.async.cg.shared.global [%0], [%1], 16;" :: "r"(dst), "l"(src))
#define CP16P(dst, src, pred) \
    asm volatile("cp.async.cg.shared.global [%0], [%1], 16, %2;" \
                 :: "r"(dst), "l"(src), "r"((pred) ? 16 : 0))
#define CP_COMMIT() asm volatile("cp.async.commit_group;" ::: "memory")
#define CP_WAIT(n)  asm volatile("cp.async.wait_group %0;" :: "n"(n) : "memory")

__device__ __forceinline__ uint32_t packh2(float x0, float x1) {
    uint32_t p;
    asm("cvt.rn.f16x2.f32 %0, %1, %2;" : "=r"(p) : "f"(x1), "f"(x0));
    return p;
}
__device__ __forceinline__ float fexp2(float x) {
    float r;
    asm("ex2.approx.ftz.f32 %0, %1;" : "=f"(r) : "f"(x));
    return r;
}

// ---------------------------------------------------------------------------
// Prep: hidden fp32->fp16 + all weight transposes (hi only), one launch
// ---------------------------------------------------------------------------
constexpr int PREP_SPLIT_BLOCKS = NTOK * HIDN / 4 / 256;  // 10240
constexpr int PREP_TOTAL_BLOCKS = PREP_SPLIT_BLOCKS + 13200;

__global__ void prep_kernel(const float* __restrict__ hidden,
                            const float* __restrict__ wqa,
                            const float* __restrict__ wkva,
                            const float* __restrict__ wqb,
                            const float* __restrict__ wkvb,
                            const float* __restrict__ wo)
{
    __shared__ float tt[32][33];
    if (blockIdx.x < PREP_SPLIT_BLOCKS) {
        const int i = blockIdx.x * 256 + threadIdx.x;
        const float4 v = *(const float4*)&hidden[(size_t)i * 4];
        *(uint2*)&g_hid_h[(size_t)i * 4] =
            make_uint2(packh2(v.x, v.y), packh2(v.z, v.w));
        return;
    }
    const int bid = blockIdx.x - PREP_SPLIT_BLOCKS;
    const float* W; __half* Th; int K, N, nx, t;
    if (bid < 1920)      { t = bid;        W=wqa;  Th=g_wqa_h;  K=HIDN;    N=Q_RANK;  nx=24; }
    else if (bid < 2640) { t = bid-1920;   W=wkva; Th=g_wkva_h; K=HIDN;    N=CKV_D;   nx=9; }
    else if (bid < 5520) { t = bid-2640;   W=wqb;  Th=g_wqb_h;  K=Q_RANK;  N=QD_ALL;  nx=120; }
    else if (bid < 6800) { t = bid-5520;   W=wkvb; Th=g_wkvb_h; K=KV_RANK; N=KVD_ALL; nx=160; }
    else                 { t = bid-6800;   W=wo;   Th=g_wo_h;   K=HIDN;    N=OD_ALL;  nx=80; }
    const int n0 = (t % nx) * 32;
    const int k0 = (t / nx) * 32;

    const int tx = threadIdx.x & 31;
    const int ty = threadIdx.x >> 5;       // 0..7
#pragma unroll
    for (int j = 0; j < 4; j++)
        tt[ty + j * 8][tx] = W[(size_t)(k0 + ty + j * 8) * N + n0 + tx];
    __syncthreads();
#pragma unroll
    for (int j = 0; j < 4; j++) {
        const float v = tt[tx][ty + j * 8];
        Th[(size_t)(n0 + ty + j * 8) * K + k0 + tx] = __float2half_rn(v);
    }
}

// ---------------------------------------------------------------------------
// Fused tensor GEMM (pure fp16, 1-product): C = A @ Bt^T
// Tile 128x128, BK=32, 2-stage cp.async pipeline (proven structure).
// ---------------------------------------------------------------------------
struct GemmDesc {
    const __half *Ah, *Bh;
    float* C;
    __half* Ch;          // fp16 out (SPLIT_OUT) or nullptr
    int N, K;
};

constexpr int GST      = 40;
constexpr int G_OFF_A  = 0;
constexpr int G_OFF_BH = 128 * GST * 2;      // 10240
constexpr int G_STAGE  = 2 * 128 * GST * 2;  // 20480
constexpr int G_SMEM   = 2 * G_STAGE;        // 40960 (2 stages)

template<bool HALF_OUT>
__global__ __launch_bounds__(256, 2)
void tgemm2_kernel(GemmDesc d0, GemmDesc d1, int xsplit)
{
    extern __shared__ char smc[];
    const uint32_t sb0 = smem_u32(smc);

    const bool second = blockIdx.x >= (unsigned)xsplit;
    const GemmDesc d = second ? d1 : d0;
    const int bx = second ? (blockIdx.x - xsplit) : blockIdx.x;
    const int N = d.N, K = d.K;

    const int tid  = threadIdx.x;
    const int warp = tid >> 5;
    const int lane = tid & 31;
    const int wr   = warp >> 1;
    const int wc   = warp & 1;
    const int row0 = blockIdx.y * 128;
    const int col0 = bx * 128;

    auto issue_chunk = [&](int ch, int st) {
        const int k0 = ch << 5;
        const uint32_t sb = sb0 + st * G_STAGE;
#pragma unroll
        for (int i = 0; i < 2; i++) {
            const int s  = tid + i * 256;
            const int r  = s >> 2;
            const int kc = (s & 3) * 8;
            const uint32_t dd = r * (GST * 2) + kc * 2;
            CP16(sb + G_OFF_A + dd, &d.Ah[(size_t)(row0 + r) * K + k0 + kc]);
            const int n = col0 + r;
            const bool pr = n < N;
            const size_t bo = (size_t)(pr ? n : 0) * K + k0 + kc;
            CP16P(sb + G_OFF_BH + dd, &d.Bh[bo], pr);
        }
    };

    float acc[2][8][4];
#pragma unroll
    for (int mf = 0; mf < 2; mf++)
#pragma unroll
        for (int nf = 0; nf < 8; nf++)
#pragma unroll
            for (int r = 0; r < 4; r++) acc[mf][nf][r] = 0.f;

    const int a_row = (lane & 15);
    const int a_col = (lane >> 4) * 8;
    const int b_row = (lane >> 4) * 8 + (lane & 7);
    const int b_col = ((lane >> 3) & 1) * 8;

    auto compute_stage = [&](int st) {
        const uint32_t Ah = sb0 + st * G_STAGE + G_OFF_A;
        const uint32_t Bh = sb0 + st * G_STAGE + G_OFF_BH;
#pragma unroll
        for (int ks = 0; ks < 32; ks += 16) {
            uint32_t ah[2][4];
#pragma unroll
            for (int mf = 0; mf < 2; mf++) {
                const uint32_t off = ((wr * 32 + mf * 16 + a_row) * GST + ks + a_col) * 2;
                ldmatrix_x4(ah[mf][0], ah[mf][1], ah[mf][2], ah[mf][3], Ah + off);
            }
#pragma unroll
            for (int np = 0; np < 4; np++) {
                uint32_t bh[4];
                const uint32_t off = ((wc * 64 + np * 16 + b_row) * GST + ks + b_col) * 2;
                ldmatrix_x4(bh[0], bh[1], bh[2], bh[3], Bh + off);
#pragma unroll
                for (int mf = 0; mf < 2; mf++) {
                    mma_f16(acc[mf][np*2],   ah[mf], bh + 0);
                    mma_f16(acc[mf][np*2+1], ah[mf], bh + 2);
                }
            }
        }
    };

    const int nch = K >> 5;
    issue_chunk(0, 0);
    CP_COMMIT();
    for (int ch = 0; ch < nch; ch++) {
        if (ch + 1 < nch) {
            issue_chunk(ch + 1, (ch + 1) & 1);
            CP_COMMIT();
            CP_WAIT(1);
        } else {
            CP_WAIT(0);
        }
        __syncthreads();
        compute_stage(ch & 1);
        __syncthreads();
    }

#pragma unroll
    for (int mf = 0; mf < 2; mf++) {
        const int r0 = row0 + wr * 32 + mf * 16 + (lane >> 2);
#pragma unroll
        for (int nf = 0; nf < 8; nf++) {
            const int c = col0 + wc * 64 + nf * 8 + (lane & 3) * 2;
            if (c < N) {
                if (HALF_OUT) {
                    *(uint32_t*)&d.Ch[(size_t)r0 * N + c] =
                        packh2(acc[mf][nf][0], acc[mf][nf][1]);
                    *(uint32_t*)&d.Ch[(size_t)(r0 + 8) * N + c] =
                        packh2(acc[mf][nf][2], acc[mf][nf][3]);
                } else {
                    *(float2*)&d.C[(size_t)r0 * N + c] =
                        make_float2(acc[mf][nf][0], acc[mf][nf][1]);
                    *(float2*)&d.C[(size_t)(r0 + 8) * N + c] =
                        make_float2(acc[mf][nf][2], acc[mf][nf][3]);
                }
            }
        }
    }
}

// ---------------------------------------------------------------------------
// Both RMSNorms in one launch -> fp16 hi plane
// ---------------------------------------------------------------------------
__global__ void rmsnorm2_kernel(const float* __restrict__ qln,
                                const float* __restrict__ kvln)
{
    const float* in; const float* w; __half* oh;
    int dim, istride, row;
    if (blockIdx.x < NTOK) {
        row = blockIdx.x;
        in = g_qa; w = qln; oh = g_qan_h;
        dim = Q_RANK; istride = Q_RANK;
    } else {
        row = blockIdx.x - NTOK;
        in = g_ckv; w = kvln; oh = g_kvn_h;
        dim = KV_RANK; istride = CKV_D;
    }
    const float* x = in + (size_t)row * istride;
    float ss = 0.f;
    for (int i = threadIdx.x; i < dim; i += blockDim.x) { float v = x[i]; ss += v * v; }
#pragma unroll
    for (int o = 16; o > 0; o >>= 1) ss += __shfl_xor_sync(0xffffffffu, ss, o);
    __shared__ float sh[8];
    __shared__ float s_inv;
    if ((threadIdx.x & 31) == 0) sh[threadIdx.x >> 5] = ss;
    __syncthreads();
    if (threadIdx.x == 0) {
        float t = 0.f;
        const int nw = blockDim.x >> 5;
        for (int i = 0; i < nw; i++) t += sh[i];
        s_inv = rsqrtf(t / (float)dim + 1e-5f);
    }
    __syncthreads();
    const float inv = s_inv;
    for (int i = threadIdx.x; i < dim; i += blockDim.x)
        oh[(size_t)row * dim + i] = __float2half_rn(x[i] * inv * w[i]);
}

// ---------------------------------------------------------------------------
// RoPE: q hi plane in-place (rope dims), ckv tail -> krot hi plane
// ---------------------------------------------------------------------------
__global__ void rope_kernel(__half* __restrict__ qh,
                            const float* __restrict__ ckv,
                            __half* __restrict__ krh,
                            const float* __restrict__ cosb, const float* __restrict__ sinb)
{
    const int token = blockIdx.x;
    const int s = token & (SEQ - 1);
    for (int i = threadIdx.x; i < (NHEAD + 1) * 32; i += blockDim.x) {
        const int h = i >> 5;
        const int d = i & 31;
        const float c  = cosb[s * ROPE_D + d];
        const float sn = sinb[s * ROPE_D + d];
        if (h < NHEAD) {
            const size_t base = (size_t)token * QD_ALL + h * QK_D + NOPE_D;
            const size_t pi   = base + ((d < 16) ? d + 16 : d - 16);
            const float x  = __half2float(qh[base + d]);
            float pr = __half2float(qh[pi]);
            if (d < 16) pr = -pr;
            __syncwarp();
            qh[base + d] = __float2half_rn(x * c + pr * sn);
        } else {
            const float* kb = ckv + (size_t)token * CKV_D + KV_RANK;
            const float x  = kb[d];
            const float pr = (d < 16) ? -kb[d + 16] : kb[d - 16];
            krh[(size_t)token * ROPE_D + d] = __float2half_rn(x * c + pr * sn);
        }
    }
}

// ---------------------------------------------------------------------------
// Flash attention, all-fp16 operands (1-product S and PV).
// BQ=128, BK=64, 256 threads, 8 warps. Largest-qt-first; K/V prefetch.
// ---------------------------------------------------------------------------
constexpr int AQ_ST = 104;
constexpr int AV_ST = 72;
constexpr int A_QT  = 128 * AQ_ST;
constexpr int A_KT  = 64 * AQ_ST;
constexpr int A_VT  = 64 * AV_ST;
constexpr int ATTN_SMEM = (A_QT + A_KT + A_VT) * (int)sizeof(__half);  // 49152

__global__ __launch_bounds__(256, 2)
void attn_mma_kernel(const __half* __restrict__ qh,
                     const __half* __restrict__ kvh,
                     const __half* __restrict__ krh,
                     __half* __restrict__ oh)
{
    extern __shared__ __half smh[];
    const uint32_t uQ  = smem_u32(smh);
    const uint32_t uKh = uQ  + A_QT * 2;
    const uint32_t uVh = uKh + A_KT * 2;

    const int bh = blockIdx.y;
    const int b  = bh / NHEAD;
    const int h  = bh % NHEAD;
    const int qt = (SEQ / 128 - 1) - blockIdx.x;   // largest work first
    const int q0 = qt * 128;
    const int tid  = threadIdx.x;
    const int warp = tid >> 5;
    const int lane = tid & 31;
    const int gr   = lane >> 2;
    const int qd   = lane & 3;
    const size_t tok0 = (size_t)b * SEQ;

    const int a_row = (lane & 15);
    const int a_col = (lane >> 4) * 8;
    const int b_row = (lane >> 4) * 8 + (lane & 7);
    const int b_col = ((lane >> 3) & 1) * 8;
    const int v_row = (lane & 15);
    const int v_col = (lane >> 4) * 8;

    auto issue_k = [&](int kt) {
        const int k0 = kt * 64;
#pragma unroll
        for (int i = 0; i < 3; i++) {
            const int s = tid + i * 256;
            if (s < 512) {
                const int r = s >> 3, c8 = (s & 7) * 8;
                const size_t src = (tok0 + k0 + r) * KVD_ALL + h * 128 + c8;
                CP16(uKh + (r * AQ_ST + c8) * 2, &kvh[src]);
            } else {
                const int t = s - 512;
                const int r = t >> 2, c8 = 64 + (t & 3) * 8;
                const size_t src = (tok0 + k0 + r) * ROPE_D + (c8 - 64);
                CP16(uKh + (r * AQ_ST + c8) * 2, &krh[src]);
            }
        }
    };
    auto issue_v = [&](int kt) {
        const int k0 = kt * 64;
#pragma unroll
        for (int i = 0; i < 2; i++) {
            const int ss = tid + i * 256;      // 0..511
            const int r = ss >> 3;
            const int c8 = (ss & 7) * 8;
            const size_t src = (tok0 + k0 + r) * KVD_ALL + h * 128 + 64 + c8;
            CP16(uVh + (r * AV_ST + c8) * 2, &kvh[src]);
        }
    };

    // ---- Q tile copy (128 x 96) ----
#pragma unroll
    for (int i = 0; i < 6; i++) {
        const int s  = tid + i * 256;        // 0..1535
        const int r  = s / 12;
        const int c8 = (s - r * 12) * 8;
        CP16(uQ + (r * AQ_ST + c8) * 2, &qh[(tok0 + q0 + r) * QD_ALL + h * QK_D + c8]);
    }
    CP_COMMIT();          // group: Q
    issue_k(0);
    CP_COMMIT();          // group: K0
    issue_v(0);
    CP_COMMIT();          // group: V0

    float oacc[8][4];
#pragma unroll
    for (int nf = 0; nf < 8; nf++)
#pragma unroll
        for (int r = 0; r < 4; r++) oacc[nf][r] = 0.f;
    float mA = -1e30f, mB = -1e30f, lA = 0.f, lB = 0.f;

    const int q0w  = q0 + warp * 16;
    const int rowA = q0w + gr;
    const int rowB = rowA + 8;
    const int nkt  = 2 * qt + 2;

    for (int kt = 0; kt < nkt; kt++) {
        const int k0 = kt * 64;

        CP_WAIT(1);            // K_t (and Q) landed; V_t may be in flight
        __syncthreads();

        // ---- S = Q @ K^T (1-product) ----
        float sa[8][4];
#pragma unroll
        for (int nf = 0; nf < 8; nf++)
#pragma unroll
            for (int r = 0; r < 4; r++) sa[nf][r] = 0.f;

#pragma unroll
        for (int ks = 0; ks < 96; ks += 16) {
            uint32_t ah[4];
            const uint32_t aoff = ((warp * 16 + a_row) * AQ_ST + ks + a_col) * 2;
            ldmatrix_x4(ah[0], ah[1], ah[2], ah[3], uQ + aoff);
#pragma unroll
            for (int np = 0; np < 4; np++) {
                uint32_t bhf[4];
                const uint32_t boff = ((np * 16 + b_row) * AQ_ST + ks + b_col) * 2;
                ldmatrix_x4(bhf[0], bhf[1], bhf[2], bhf[3], uKh + boff);
                mma_f16(sa[np*2],   ah, bhf + 0);
                mma_f16(sa[np*2+1], ah, bhf + 2);
            }
        }
        __syncthreads();       // all warps done reading K smem
        if (kt + 1 < nkt) issue_k(kt + 1);
        CP_COMMIT();           // group K_{t+1} (possibly empty)

        // ---- scale + mask ----
#pragma unroll
        for (int nf = 0; nf < 8; nf++)
#pragma unroll
            for (int r = 0; r < 4; r++) sa[nf][r] *= SC2;
        if (k0 + 63 > q0w) {
#pragma unroll
            for (int nf = 0; nf < 8; nf++) {
                const int col = k0 + nf * 8 + qd * 2;
                if (col     > rowA) sa[nf][0] = -1e30f;
                if (col + 1 > rowA) sa[nf][1] = -1e30f;
                if (col     > rowB) sa[nf][2] = -1e30f;
                if (col + 1 > rowB) sa[nf][3] = -1e30f;
            }
        }

        // ---- online softmax ----
        float mxA = -1e30f, mxB = -1e30f;
#pragma unroll
        for (int nf = 0; nf < 8; nf++) {
            mxA = fmaxf(mxA, fmaxf(sa[nf][0], sa[nf][1]));
            mxB = fmaxf(mxB, fmaxf(sa[nf][2], sa[nf][3]));
        }
        mxA = fmaxf(mxA, __shfl_xor_sync(0xffffffffu, mxA, 1));
        mxA = fmaxf(mxA, __shfl_xor_sync(0xffffffffu, mxA, 2));
        mxB = fmaxf(mxB, __shfl_xor_sync(0xffffffffu, mxB, 1));
        mxB = fmaxf(mxB, __shfl_xor_sync(0xffffffffu, mxB, 2));
        const float mnA = fmaxf(mA, mxA);
        const float mnB = fmaxf(mB, mxB);
        const float alA = fexp2(mA - mnA);
        const float alB = fexp2(mB - mnB);
        mA = mnA; mB = mnB;

        float rsA = 0.f, rsB = 0.f;
#pragma unroll
        for (int nf = 0; nf < 8; nf++) {
            sa[nf][0] = fexp2(sa[nf][0] - mnA); rsA += sa[nf][0];
            sa[nf][1] = fexp2(sa[nf][1] - mnA); rsA += sa[nf][1];
            sa[nf][2] = fexp2(sa[nf][2] - mnB); rsB += sa[nf][2];
            sa[nf][3] = fexp2(sa[nf][3] - mnB); rsB += sa[nf][3];
        }
        rsA += __shfl_xor_sync(0xffffffffu, rsA, 1);
        rsA += __shfl_xor_sync(0xffffffffu, rsA, 2);
        rsB += __shfl_xor_sync(0xffffffffu, rsB, 1);
        rsB += __shfl_xor_sync(0xffffffffu, rsB, 2);
        lA = lA * alA + rsA;
        lB = lB * alB + rsB;
#pragma unroll
        for (int nf = 0; nf < 8; nf++) {
            oacc[nf][0] *= alA; oacc[nf][1] *= alA;
            oacc[nf][2] *= alB; oacc[nf][3] *= alB;
        }

        CP_WAIT(1);            // V_t landed; K_{t+1} may be in flight
        __syncthreads();

        // ---- O += P @ V  (1-product) ----
#pragma unroll
        for (int t = 0; t < 4; t++) {
            uint32_t ph[4];
            ph[0] = packh2(sa[2*t][0],   sa[2*t][1]);
            ph[1] = packh2(sa[2*t][2],   sa[2*t][3]);
            ph[2] = packh2(sa[2*t+1][0], sa[2*t+1][1]);
            ph[3] = packh2(sa[2*t+1][2], sa[2*t+1][3]);
#pragma unroll
            for (int np = 0; np < 4; np++) {
                uint32_t vhf[4];
                const uint32_t voff = ((t * 16 + v_row) * AV_ST + np * 16 + v_col) * 2;
                ldmatrix_x4_t(vhf[0], vhf[1], vhf[2], vhf[3], uVh + voff);
                mma_f16(oacc[np*2],   ph, vhf + 0);
                mma_f16(oacc[np*2+1], ph, vhf + 2);
            }
        }
        __syncthreads();       // all warps done reading V smem
        if (kt + 1 < nkt) issue_v(kt + 1);
        CP_COMMIT();           // group V_{t+1} (possibly empty)
    }

    // ---- finalize + write ----
    const float invA = 1.f / lA;
    const float invB = 1.f / lB;
#pragma unroll
    for (int nf = 0; nf < 8; nf++) {
        const int col = h * V_D + nf * 8 + qd * 2;
        *(uint32_t*)&oh[(tok0 + rowA) * (size_t)OD_ALL + col] =
            packh2(oacc[nf][0] * invA, oacc[nf][1] * invA);
        *(uint32_t*)&oh[(tok0 + rowB) * (size_t)OD_ALL + col] =
            packh2(oacc[nf][2] * invB, oacc[nf][3] * invB);
    }
}

// ---------------------------------------------------------------------------
// Launch
// ---------------------------------------------------------------------------
extern "C" void kernel_launch(void* const* d_in, const int* in_sizes, int n_in,
                              void* d_out, int out_size)
{
    const float* hidden = (const float*)d_in[0];
    const float* cosb   = (const float*)d_in[1];
    const float* sinb   = (const float*)d_in[2];
    const float* wq_a   = (const float*)d_in[3];
    const float* q_ln   = (const float*)d_in[4];
    const float* wq_b   = (const float*)d_in[5];
    const float* wkv_a  = (const float*)d_in[6];
    const float* kv_ln  = (const float*)d_in[7];
    const float* wkv_b  = (const float*)d_in[8];
    const float* wo     = (const float*)d_in[9];
    float* out = (float*)d_out;

    __half *hidh, *wqah, *wkvah, *wqbh, *wkvbh, *woh, *qanh, *kvnh,
           *qhp, *kvhp, *krhp, *ath;
    float *qa, *ckv;
    cudaGetSymbolAddress((void**)&hidh,  g_hid_h);
    cudaGetSymbolAddress((void**)&wqah,  g_wqa_h);
    cudaGetSymbolAddress((void**)&wkvah, g_wkva_h);
    cudaGetSymbolAddress((void**)&wqbh,  g_wqb_h);
    cudaGetSymbolAddress((void**)&wkvbh, g_wkvb_h);
    cudaGetSymbolAddress((void**)&woh,   g_wo_h);
    cudaGetSymbolAddress((void**)&qa,    g_qa);
    cudaGetSymbolAddress((void**)&ckv,   g_ckv);
    cudaGetSymbolAddress((void**)&qanh,  g_qan_h);
    cudaGetSymbolAddress((void**)&kvnh,  g_kvn_h);
    cudaGetSymbolAddress((void**)&qhp,   g_q_h);
    cudaGetSymbolAddress((void**)&kvhp,  g_kv_h);
    cudaGetSymbolAddress((void**)&krhp,  g_kr_h);
    cudaGetSymbolAddress((void**)&ath,   g_at_h);

    cudaFuncSetAttribute((const void*)tgemm2_kernel<false>,
                         cudaFuncAttributeMaxDynamicSharedMemorySize, G_SMEM);
    cudaFuncSetAttribute((const void*)tgemm2_kernel<true>,
                         cudaFuncAttributeMaxDynamicSharedMemorySize, G_SMEM);
    cudaFuncSetAttribute((const void*)attn_mma_kernel,
                         cudaFuncAttributeMaxDynamicSharedMemorySize, ATTN_SMEM);

    const dim3 blk(256);
    const int mt = NTOK / 128;

    // 0: prep (hidden convert + all weight transposes)
    prep_kernel<<<PREP_TOTAL_BLOCKS, 256>>>(hidden, wq_a, wkv_a, wq_b, wkv_b, wo);

    // 1: fused GEMM pair: qa = hid@wqa  |  ckv = hid@wkva   (fp32 out)
    {
        GemmDesc d0 = { hidh, wqah,  qa,  nullptr, Q_RANK, HIDN };
        GemmDesc d1 = { hidh, wkvah, ckv, nullptr, CKV_D,  HIDN };
        tgemm2_kernel<false><<<dim3(6 + 3, mt), blk, G_SMEM>>>(d0, d1, 6);
    }
    // 2: both rmsnorms -> fp16 planes
    rmsnorm2_kernel<<<2 * NTOK, 256>>>(q_ln, kv_ln);
    // 3: fused GEMM pair: q = qan@wqb | kv = kvn@wkvb  (fp16 outs)
    {
        GemmDesc d0 = { qanh, wqbh,  nullptr, qhp,  QD_ALL,  Q_RANK };
        GemmDesc d1 = { kvnh, wkvbh, nullptr, kvhp, KVD_ALL, KV_RANK };
        tgemm2_kernel<true><<<dim3(30 + 40, mt), blk, G_SMEM>>>(d0, d1, 30);
    }
    // 4: rope
    rope_kernel<<<NTOK, 256>>>(qhp, ckv, krhp, cosb, sinb);
    // 5: attention (largest qt first, all-fp16 1-product)
    attn_mma_kernel<<<dim3(SEQ / 128, 2 * NHEAD), blk, ATTN_SMEM>>>(
        qhp, kvhp, krhp, ath);
    // 6: out = attn @ wo
    {
        GemmDesc d0 = { ath, woh, out, nullptr, HIDN, OD_ALL };
        tgemm2_kernel<false><<<dim3(HIDN / 128, mt), blk, G_SMEM>>>(d0, d0, HIDN / 128);
    }
}

// round 15
// speedup vs baseline: 2.0808x; 1.0717x over previous
#include <cuda_runtime.h>
#include <cuda_fp16.h>
#include <cstdint>

// ---------------------------------------------------------------------------
// Problem constants
// ---------------------------------------------------------------------------
constexpr int SEQ    = 2048;
constexpr int HIDN   = 2560;
constexpr int NHEAD  = 40;
constexpr int NOPE_D = 64;
constexpr int ROPE_D = 32;
constexpr int QK_D   = NOPE_D + ROPE_D;    // 96
constexpr int V_D    = 64;
constexpr int Q_RANK = 768;
constexpr int KV_RANK= 256;
constexpr int CKV_D  = KV_RANK + ROPE_D;   // 288
constexpr int NTOK   = 2 * SEQ;            // 4096
constexpr int QD_ALL = NHEAD * QK_D;       // 3840
constexpr int KVD_ALL= NHEAD * (NOPE_D + V_D); // 5120
constexpr int OD_ALL = NHEAD * V_D;        // 2560
constexpr float SCALE = 0.10206207261596577f;
constexpr float SC2   = SCALE * 1.4426950408889634f;

// ---------------------------------------------------------------------------
// Scratch (all fp16, fp32 only for pre-norm intermediates)
// ---------------------------------------------------------------------------
__device__ __half g_hid_h [NTOK * HIDN];
__device__ __half g_wqa_h [Q_RANK * HIDN];     // transposed [N][K]
__device__ __half g_wkva_h[CKV_D * HIDN];
__device__ __half g_wqb_h [QD_ALL * Q_RANK];
__device__ __half g_wkvb_h[KVD_ALL * KV_RANK];
__device__ __half g_wo_h  [HIDN * OD_ALL];
__device__ float  g_qa    [NTOK * Q_RANK];
__device__ float  g_ckv   [NTOK * CKV_D];
__device__ __half g_qan_h [NTOK * Q_RANK];
__device__ __half g_kvn_h [NTOK * KV_RANK];
__device__ __half g_q_h   [NTOK * QD_ALL];
__device__ __half g_kv_h  [NTOK * KVD_ALL];
__device__ __half g_kr_h  [NTOK * ROPE_D];
__device__ __half g_at_h  [NTOK * OD_ALL];

// ---------------------------------------------------------------------------
// PTX helpers (portable sm_80+ subset)
// ---------------------------------------------------------------------------
__device__ __forceinline__ uint32_t smem_u32(const void* p) {
    uint32_t a;
    asm("{ .reg .u64 t; cvta.to.shared.u64 t, %1; cvt.u32.u64 %0, t; }"
        : "=r"(a) : "l"(p));
    return a;
}
__device__ __forceinline__ void ldmatrix_x4(uint32_t& r0, uint32_t& r1,
                                            uint32_t& r2, uint32_t& r3, uint32_t addr) {
    asm volatile("ldmatrix.sync.aligned.m8n8.x4.shared.b16 {%0,%1,%2,%3}, [%4];"
                 : "=r"(r0), "=r"(r1), "=r"(r2), "=r"(r3) : "r"(addr));
}
__device__ __forceinline__ void ldmatrix_x4_t(uint32_t& r0, uint32_t& r1,
                                              uint32_t& r2, uint32_t& r3, uint32_t addr) {
    asm volatile("ldmatrix.sync.aligned.m8n8.x4.trans.shared.b16 {%0,%1,%2,%3}, [%4];"
                 : "=r"(r0), "=r"(r1), "=r"(r2), "=r"(r3) : "r"(addr));
}
__device__ __forceinline__ void mma_f16(float* c, const uint32_t* a, const uint32_t* b) {
    asm volatile(
        "mma.sync.aligned.m16n8k16.row.col.f32.f16.f16.f32 "
        "{%0,%1,%2,%3}, {%4,%5,%6,%7}, {%8,%9}, {%0,%1,%2,%3};"
        : "+f"(c[0]), "+f"(c[1]), "+f"(c[2]), "+f"(c[3])
        : "r"(a[0]), "r"(a[1]), "r"(a[2]), "r"(a[3]), "r"(b[0]), "r"(b[1]));
}
#define CP16(dst, src) \
    asm volatile("cp.async.cg.shared.global [%0], [%1], 16;" :: "r"(dst), "l"(src))
#define CP16P(dst, src, pred) \
    asm volatile("cp.async.cg.shared.global [%0], [%1], 16, %2;" \
                 :: "r"(dst), "l"(src), "r"((pred) ? 16 : 0))
#define CP_COMMIT() asm volatile("cp.async.commit_group;" ::: "memory")
#define CP_WAIT(n)  asm volatile("cp.async.wait_group %0;" :: "n"(n) : "memory")

__device__ __forceinline__ uint32_t packh2(float x0, float x1) {
    uint32_t p;
    asm("cvt.rn.f16x2.f32 %0, %1, %2;" : "=r"(p) : "f"(x1), "f"(x0));
    return p;
}
__device__ __forceinline__ float fexp2(float x) {
    float r;
    asm("ex2.approx.ftz.f32 %0, %1;" : "=f"(r) : "f"(x));
    return r;
}

// ---------------------------------------------------------------------------
// Prep: hidden fp32->fp16 + all weight transposes, one launch
// ---------------------------------------------------------------------------
constexpr int PREP_SPLIT_BLOCKS = NTOK * HIDN / 4 / 256;  // 10240
constexpr int PREP_TOTAL_BLOCKS = PREP_SPLIT_BLOCKS + 13200;

__global__ void prep_kernel(const float* __restrict__ hidden,
                            const float* __restrict__ wqa,
                            const float* __restrict__ wkva,
                            const float* __restrict__ wqb,
                            const float* __restrict__ wkvb,
                            const float* __restrict__ wo)
{
    __shared__ float tt[32][33];
    if (blockIdx.x < PREP_SPLIT_BLOCKS) {
        const int i = blockIdx.x * 256 + threadIdx.x;
        const float4 v = *(const float4*)&hidden[(size_t)i * 4];
        *(uint2*)&g_hid_h[(size_t)i * 4] =
            make_uint2(packh2(v.x, v.y), packh2(v.z, v.w));
        return;
    }
    const int bid = blockIdx.x - PREP_SPLIT_BLOCKS;
    const float* W; __half* Th; int K, N, nx, t;
    if (bid < 1920)      { t = bid;        W=wqa;  Th=g_wqa_h;  K=HIDN;    N=Q_RANK;  nx=24; }
    else if (bid < 2640) { t = bid-1920;   W=wkva; Th=g_wkva_h; K=HIDN;    N=CKV_D;   nx=9; }
    else if (bid < 5520) { t = bid-2640;   W=wqb;  Th=g_wqb_h;  K=Q_RANK;  N=QD_ALL;  nx=120; }
    else if (bid < 6800) { t = bid-5520;   W=wkvb; Th=g_wkvb_h; K=KV_RANK; N=KVD_ALL; nx=160; }
    else                 { t = bid-6800;   W=wo;   Th=g_wo_h;   K=HIDN;    N=OD_ALL;  nx=80; }
    const int n0 = (t % nx) * 32;
    const int k0 = (t / nx) * 32;

    const int tx = threadIdx.x & 31;
    const int ty = threadIdx.x >> 5;       // 0..7
#pragma unroll
    for (int j = 0; j < 4; j++)
        tt[ty + j * 8][tx] = W[(size_t)(k0 + ty + j * 8) * N + n0 + tx];
    __syncthreads();
#pragma unroll
    for (int j = 0; j < 4; j++) {
        const float v = tt[tx][ty + j * 8];
        Th[(size_t)(n0 + ty + j * 8) * K + k0 + tx] = __float2half_rn(v);
    }
}

// ---------------------------------------------------------------------------
// Fused tensor GEMM (pure fp16): C = A @ Bt^T
// Tile 128x128, BK=64 (halved barrier count), 2-stage cp.async pipeline.
// ---------------------------------------------------------------------------
struct GemmDesc {
    const __half *Ah, *Bh;
    float* C;
    __half* Ch;
    int N, K;
};

constexpr int GST      = 72;                 // 64 + 8 pad (conflict-free ldmatrix)
constexpr int G_OFF_A  = 0;
constexpr int G_OFF_B  = 128 * GST * 2;      // 18432
constexpr int G_STAGE  = 2 * 128 * GST * 2;  // 36864
constexpr int G_SMEM   = 2 * G_STAGE;        // 73728 (2 stages)

template<bool HALF_OUT>
__global__ __launch_bounds__(256, 2)
void tgemm2_kernel(GemmDesc d0, GemmDesc d1, int xsplit)
{
    extern __shared__ char smc[];
    const uint32_t sb0 = smem_u32(smc);

    const bool second = blockIdx.x >= (unsigned)xsplit;
    const GemmDesc d = second ? d1 : d0;
    const int bx = second ? (blockIdx.x - xsplit) : blockIdx.x;
    const int N = d.N, K = d.K;

    const int tid  = threadIdx.x;
    const int warp = tid >> 5;
    const int lane = tid & 31;
    const int wr   = warp >> 1;
    const int wc   = warp & 1;
    const int row0 = blockIdx.y * 128;
    const int col0 = bx * 128;

    auto issue_chunk = [&](int ch, int st) {
        const int k0 = ch << 6;
        const uint32_t sb = sb0 + st * G_STAGE;
#pragma unroll
        for (int i = 0; i < 4; i++) {
            const int s  = tid + i * 256;      // 0..1023
            const int r  = s >> 3;             // 0..127
            const int kc = (s & 7) * 8;        // 0..56
            const uint32_t dd = r * (GST * 2) + kc * 2;
            CP16(sb + G_OFF_A + dd, &d.Ah[(size_t)(row0 + r) * K + k0 + kc]);
            const int n = col0 + r;
            const bool pr = n < N;
            const size_t bo = (size_t)(pr ? n : 0) * K + k0 + kc;
            CP16P(sb + G_OFF_B + dd, &d.Bh[bo], pr);
        }
    };

    float acc[2][8][4];
#pragma unroll
    for (int mf = 0; mf < 2; mf++)
#pragma unroll
        for (int nf = 0; nf < 8; nf++)
#pragma unroll
            for (int r = 0; r < 4; r++) acc[mf][nf][r] = 0.f;

    const int a_row = (lane & 15);
    const int a_col = (lane >> 4) * 8;
    const int b_row = (lane >> 4) * 8 + (lane & 7);
    const int b_col = ((lane >> 3) & 1) * 8;

    auto compute_stage = [&](int st) {
        const uint32_t Ah = sb0 + st * G_STAGE + G_OFF_A;
        const uint32_t Bh = sb0 + st * G_STAGE + G_OFF_B;
#pragma unroll
        for (int ks = 0; ks < 64; ks += 16) {
            uint32_t ah[2][4];
#pragma unroll
            for (int mf = 0; mf < 2; mf++) {
                const uint32_t off = ((wr * 32 + mf * 16 + a_row) * GST + ks + a_col) * 2;
                ldmatrix_x4(ah[mf][0], ah[mf][1], ah[mf][2], ah[mf][3], Ah + off);
            }
#pragma unroll
            for (int np = 0; np < 4; np++) {
                uint32_t bh[4];
                const uint32_t off = ((wc * 64 + np * 16 + b_row) * GST + ks + b_col) * 2;
                ldmatrix_x4(bh[0], bh[1], bh[2], bh[3], Bh + off);
#pragma unroll
                for (int mf = 0; mf < 2; mf++) {
                    mma_f16(acc[mf][np*2],   ah[mf], bh + 0);
                    mma_f16(acc[mf][np*2+1], ah[mf], bh + 2);
                }
            }
        }
    };

    const int nch = K >> 6;
    issue_chunk(0, 0);
    CP_COMMIT();
    for (int ch = 0; ch < nch; ch++) {
        if (ch + 1 < nch) {
            issue_chunk(ch + 1, (ch + 1) & 1);
            CP_COMMIT();
            CP_WAIT(1);
        } else {
            CP_WAIT(0);
        }
        __syncthreads();
        compute_stage(ch & 1);
        __syncthreads();
    }

#pragma unroll
    for (int mf = 0; mf < 2; mf++) {
        const int r0 = row0 + wr * 32 + mf * 16 + (lane >> 2);
#pragma unroll
        for (int nf = 0; nf < 8; nf++) {
            const int c = col0 + wc * 64 + nf * 8 + (lane & 3) * 2;
            if (c < N) {
                if (HALF_OUT) {
                    *(uint32_t*)&d.Ch[(size_t)r0 * N + c] =
                        packh2(acc[mf][nf][0], acc[mf][nf][1]);
                    *(uint32_t*)&d.Ch[(size_t)(r0 + 8) * N + c] =
                        packh2(acc[mf][nf][2], acc[mf][nf][3]);
                } else {
                    *(float2*)&d.C[(size_t)r0 * N + c] =
                        make_float2(acc[mf][nf][0], acc[mf][nf][1]);
                    *(float2*)&d.C[(size_t)(r0 + 8) * N + c] =
                        make_float2(acc[mf][nf][2], acc[mf][nf][3]);
                }
            }
        }
    }
}

// ---------------------------------------------------------------------------
// Both RMSNorms in one launch -> fp16
// ---------------------------------------------------------------------------
__global__ void rmsnorm2_kernel(const float* __restrict__ qln,
                                const float* __restrict__ kvln)
{
    const float* in; const float* w; __half* oh;
    int dim, istride, row;
    if (blockIdx.x < NTOK) {
        row = blockIdx.x;
        in = g_qa; w = qln; oh = g_qan_h;
        dim = Q_RANK; istride = Q_RANK;
    } else {
        row = blockIdx.x - NTOK;
        in = g_ckv; w = kvln; oh = g_kvn_h;
        dim = KV_RANK; istride = CKV_D;
    }
    const float* x = in + (size_t)row * istride;
    float ss = 0.f;
    for (int i = threadIdx.x; i < dim; i += blockDim.x) { float v = x[i]; ss += v * v; }
#pragma unroll
    for (int o = 16; o > 0; o >>= 1) ss += __shfl_xor_sync(0xffffffffu, ss, o);
    __shared__ float sh[8];
    __shared__ float s_inv;
    if ((threadIdx.x & 31) == 0) sh[threadIdx.x >> 5] = ss;
    __syncthreads();
    if (threadIdx.x == 0) {
        float t = 0.f;
        const int nw = blockDim.x >> 5;
        for (int i = 0; i < nw; i++) t += sh[i];
        s_inv = rsqrtf(t / (float)dim + 1e-5f);
    }
    __syncthreads();
    const float inv = s_inv;
    for (int i = threadIdx.x; i < dim; i += blockDim.x)
        oh[(size_t)row * dim + i] = __float2half_rn(x[i] * inv * w[i]);
}

// ---------------------------------------------------------------------------
// RoPE: q fp16 in-place (rope dims), ckv tail -> krot fp16
// ---------------------------------------------------------------------------
__global__ void rope_kernel(__half* __restrict__ qh,
                            const float* __restrict__ ckv,
                            __half* __restrict__ krh,
                            const float* __restrict__ cosb, const float* __restrict__ sinb)
{
    const int token = blockIdx.x;
    const int s = token & (SEQ - 1);
    for (int i = threadIdx.x; i < (NHEAD + 1) * 32; i += blockDim.x) {
        const int h = i >> 5;
        const int d = i & 31;
        const float c  = cosb[s * ROPE_D + d];
        const float sn = sinb[s * ROPE_D + d];
        if (h < NHEAD) {
            const size_t base = (size_t)token * QD_ALL + h * QK_D + NOPE_D;
            const size_t pi   = base + ((d < 16) ? d + 16 : d - 16);
            const float x  = __half2float(qh[base + d]);
            float pr = __half2float(qh[pi]);
            if (d < 16) pr = -pr;
            __syncwarp();
            qh[base + d] = __float2half_rn(x * c + pr * sn);
        } else {
            const float* kb = ckv + (size_t)token * CKV_D + KV_RANK;
            const float x  = kb[d];
            const float pr = (d < 16) ? -kb[d + 16] : kb[d - 16];
            krh[(size_t)token * ROPE_D + d] = __float2half_rn(x * c + pr * sn);
        }
    }
}

// ---------------------------------------------------------------------------
// Flash attention, all-fp16. 3-buffer K/V ring, prefetch distance 2,
// ONE wait + ONE barrier per tile. BQ=128, BK=64, 256 threads, 8 warps.
// ---------------------------------------------------------------------------
constexpr int AQ_ST = 104;
constexpr int AV_ST = 72;
constexpr int A_QT  = 128 * AQ_ST;   // 13312
constexpr int A_KT  = 64 * AQ_ST;    // 6656
constexpr int A_VT  = 64 * AV_ST;    // 4608
constexpr int ATTN_SMEM = (A_QT + 3 * A_KT + 3 * A_VT) * (int)sizeof(__half); // 94208

__global__ __launch_bounds__(256, 2)
void attn_mma_kernel(const __half* __restrict__ qh,
                     const __half* __restrict__ kvh,
                     const __half* __restrict__ krh,
                     __half* __restrict__ oh)
{
    extern __shared__ __half smh[];
    const uint32_t uQ  = smem_u32(smh);
    const uint32_t uK0 = uQ  + A_QT * 2;
    const uint32_t uV0 = uK0 + 3 * A_KT * 2;

    const int bh = blockIdx.y;
    const int b  = bh / NHEAD;
    const int h  = bh % NHEAD;
    const int qt = (SEQ / 128 - 1) - blockIdx.x;   // largest work first
    const int q0 = qt * 128;
    const int tid  = threadIdx.x;
    const int warp = tid >> 5;
    const int lane = tid & 31;
    const int gr   = lane >> 2;
    const int qd   = lane & 3;
    const size_t tok0 = (size_t)b * SEQ;

    const int a_row = (lane & 15);
    const int a_col = (lane >> 4) * 8;
    const int b_row = (lane >> 4) * 8 + (lane & 7);
    const int b_col = ((lane >> 3) & 1) * 8;
    const int v_row = (lane & 15);
    const int v_col = (lane >> 4) * 8;

    auto issue_k = [&](int kt, int buf) {
        const int k0 = kt * 64;
        const uint32_t uK = uK0 + buf * (A_KT * 2);
#pragma unroll
        for (int i = 0; i < 3; i++) {
            const int s = tid + i * 256;
            if (s < 512) {
                const int r = s >> 3, c8 = (s & 7) * 8;
                const size_t src = (tok0 + k0 + r) * KVD_ALL + h * 128 + c8;
                CP16(uK + (r * AQ_ST + c8) * 2, &kvh[src]);
            } else {
                const int t = s - 512;
                const int r = t >> 2, c8 = 64 + (t & 3) * 8;
                const size_t src = (tok0 + k0 + r) * ROPE_D + (c8 - 64);
                CP16(uK + (r * AQ_ST + c8) * 2, &krh[src]);
            }
        }
    };
    auto issue_v = [&](int kt, int buf) {
        const int k0 = kt * 64;
        const uint32_t uV = uV0 + buf * (A_VT * 2);
#pragma unroll
        for (int i = 0; i < 2; i++) {
            const int ss = tid + i * 256;      // 0..511
            const int r = ss >> 3;
            const int c8 = (ss & 7) * 8;
            const size_t src = (tok0 + k0 + r) * KVD_ALL + h * 128 + 64 + c8;
            CP16(uV + (r * AV_ST + c8) * 2, &kvh[src]);
        }
    };

    const int nkt = 2 * qt + 2;

    // ---- prologue: Q + K0 | V0 | K1 | V1 (4 groups) ----
#pragma unroll
    for (int i = 0; i < 6; i++) {
        const int s  = tid + i * 256;        // 0..1535
        const int r  = s / 12;
        const int c8 = (s - r * 12) * 8;
        CP16(uQ + (r * AQ_ST + c8) * 2, &qh[(tok0 + q0 + r) * QD_ALL + h * QK_D + c8]);
    }
    issue_k(0, 0);
    CP_COMMIT();                       // group: Q+K0
    issue_v(0, 0);
    CP_COMMIT();                       // group: V0
    if (1 < nkt) issue_k(1, 1);
    CP_COMMIT();                       // group: K1
    if (1 < nkt) issue_v(1, 1);
    CP_COMMIT();                       // group: V1

    float oacc[8][4];
#pragma unroll
    for (int nf = 0; nf < 8; nf++)
#pragma unroll
        for (int r = 0; r < 4; r++) oacc[nf][r] = 0.f;
    float mA = -1e30f, mB = -1e30f, lA = 0.f, lB = 0.f;

    const int q0w  = q0 + warp * 16;
    const int rowA = q0w + gr;
    const int rowB = rowA + 8;

    for (int kt = 0; kt < nkt; kt++) {
        const int k0  = kt * 64;
        const int buf = kt % 3;
        const uint32_t uK = uK0 + buf * (A_KT * 2);
        const uint32_t uV = uV0 + buf * (A_VT * 2);

        CP_WAIT(2);            // K_t and V_t (and Q) landed
        __syncthreads();       // cross-warp visibility + buffer-reuse fence

        // prefetch tile t+2 into buffer (t+2)%3 (safe: last read at t-1)
        if (kt + 2 < nkt) issue_k(kt + 2, (kt + 2) % 3);
        CP_COMMIT();
        if (kt + 2 < nkt) issue_v(kt + 2, (kt + 2) % 3);
        CP_COMMIT();

        // ---- S = Q @ K^T ----
        float sa[8][4];
#pragma unroll
        for (int nf = 0; nf < 8; nf++)
#pragma unroll
            for (int r = 0; r < 4; r++) sa[nf][r] = 0.f;

#pragma unroll
        for (int ks = 0; ks < 96; ks += 16) {
            uint32_t ah[4];
            const uint32_t aoff = ((warp * 16 + a_row) * AQ_ST + ks + a_col) * 2;
            ldmatrix_x4(ah[0], ah[1], ah[2], ah[3], uQ + aoff);
#pragma unroll
            for (int np = 0; np < 4; np++) {
                uint32_t bhf[4];
                const uint32_t boff = ((np * 16 + b_row) * AQ_ST + ks + b_col) * 2;
                ldmatrix_x4(bhf[0], bhf[1], bhf[2], bhf[3], uK + boff);
                mma_f16(sa[np*2],   ah, bhf + 0);
                mma_f16(sa[np*2+1], ah, bhf + 2);
            }
        }

        // ---- scale + mask ----
#pragma unroll
        for (int nf = 0; nf < 8; nf++)
#pragma unroll
            for (int r = 0; r < 4; r++) sa[nf][r] *= SC2;
        if (k0 + 63 > q0w) {
#pragma unroll
            for (int nf = 0; nf < 8; nf++) {
                const int col = k0 + nf * 8 + qd * 2;
                if (col     > rowA) sa[nf][0] = -1e30f;
                if (col + 1 > rowA) sa[nf][1] = -1e30f;
                if (col     > rowB) sa[nf][2] = -1e30f;
                if (col + 1 > rowB) sa[nf][3] = -1e30f;
            }
        }

        // ---- online softmax ----
        float mxA = -1e30f, mxB = -1e30f;
#pragma unroll
        for (int nf = 0; nf < 8; nf++) {
            mxA = fmaxf(mxA, fmaxf(sa[nf][0], sa[nf][1]));
            mxB = fmaxf(mxB, fmaxf(sa[nf][2], sa[nf][3]));
        }
        mxA = fmaxf(mxA, __shfl_xor_sync(0xffffffffu, mxA, 1));
        mxA = fmaxf(mxA, __shfl_xor_sync(0xffffffffu, mxA, 2));
        mxB = fmaxf(mxB, __shfl_xor_sync(0xffffffffu, mxB, 1));
        mxB = fmaxf(mxB, __shfl_xor_sync(0xffffffffu, mxB, 2));
        const float mnA = fmaxf(mA, mxA);
        const float mnB = fmaxf(mB, mxB);
        const float alA = fexp2(mA - mnA);
        const float alB = fexp2(mB - mnB);
        mA = mnA; mB = mnB;

        float rsA = 0.f, rsB = 0.f;
#pragma unroll
        for (int nf = 0; nf < 8; nf++) {
            sa[nf][0] = fexp2(sa[nf][0] - mnA); rsA += sa[nf][0];
            sa[nf][1] = fexp2(sa[nf][1] - mnA); rsA += sa[nf][1];
            sa[nf][2] = fexp2(sa[nf][2] - mnB); rsB += sa[nf][2];
            sa[nf][3] = fexp2(sa[nf][3] - mnB); rsB += sa[nf][3];
        }
        rsA += __shfl_xor_sync(0xffffffffu, rsA, 1);
        rsA += __shfl_xor_sync(0xffffffffu, rsA, 2);
        rsB += __shfl_xor_sync(0xffffffffu, rsB, 1);
        rsB += __shfl_xor_sync(0xffffffffu, rsB, 2);
        lA = lA * alA + rsA;
        lB = lB * alB + rsB;
#pragma unroll
        for (int nf = 0; nf < 8; nf++) {
            oacc[nf][0] *= alA; oacc[nf][1] *= alA;
            oacc[nf][2] *= alB; oacc[nf][3] *= alB;
        }

        // ---- O += P @ V ----
#pragma unroll
        for (int t = 0; t < 4; t++) {
            uint32_t ph[4];
            ph[0] = packh2(sa[2*t][0],   sa[2*t][1]);
            ph[1] = packh2(sa[2*t][2],   sa[2*t][3]);
            ph[2] = packh2(sa[2*t+1][0], sa[2*t+1][1]);
            ph[3] = packh2(sa[2*t+1][2], sa[2*t+1][3]);
#pragma unroll
            for (int np = 0; np < 4; np++) {
                uint32_t vhf[4];
                const uint32_t voff = ((t * 16 + v_row) * AV_ST + np * 16 + v_col) * 2;
                ldmatrix_x4_t(vhf[0], vhf[1], vhf[2], vhf[3], uV + voff);
                mma_f16(oacc[np*2],   ph, vhf + 0);
                mma_f16(oacc[np*2+1], ph, vhf + 2);
            }
        }
    }

    // ---- finalize + write ----
    const float invA = 1.f / lA;
    const float invB = 1.f / lB;
#pragma unroll
    for (int nf = 0; nf < 8; nf++) {
        const int col = h * V_D + nf * 8 + qd * 2;
        *(uint32_t*)&oh[(tok0 + rowA) * (size_t)OD_ALL + col] =
            packh2(oacc[nf][0] * invA, oacc[nf][1] * invA);
        *(uint32_t*)&oh[(tok0 + rowB) * (size_t)OD_ALL + col] =
            packh2(oacc[nf][2] * invB, oacc[nf][3] * invB);
    }
}

// ---------------------------------------------------------------------------
// Launch
// ---------------------------------------------------------------------------
extern "C" void kernel_launch(void* const* d_in, const int* in_sizes, int n_in,
                              void* d_out, int out_size)
{
    const float* hidden = (const float*)d_in[0];
    const float* cosb   = (const float*)d_in[1];
    const float* sinb   = (const float*)d_in[2];
    const float* wq_a   = (const float*)d_in[3];
    const float* q_ln   = (const float*)d_in[4];
    const float* wq_b   = (const float*)d_in[5];
    const float* wkv_a  = (const float*)d_in[6];
    const float* kv_ln  = (const float*)d_in[7];
    const float* wkv_b  = (const float*)d_in[8];
    const float* wo     = (const float*)d_in[9];
    float* out = (float*)d_out;

    __half *hidh, *wqah, *wkvah, *wqbh, *wkvbh, *woh, *qanh, *kvnh,
           *qhp, *kvhp, *krhp, *ath;
    float *qa, *ckv;
    cudaGetSymbolAddress((void**)&hidh,  g_hid_h);
    cudaGetSymbolAddress((void**)&wqah,  g_wqa_h);
    cudaGetSymbolAddress((void**)&wkvah, g_wkva_h);
    cudaGetSymbolAddress((void**)&wqbh,  g_wqb_h);
    cudaGetSymbolAddress((void**)&wkvbh, g_wkvb_h);
    cudaGetSymbolAddress((void**)&woh,   g_wo_h);
    cudaGetSymbolAddress((void**)&qa,    g_qa);
    cudaGetSymbolAddress((void**)&ckv,   g_ckv);
    cudaGetSymbolAddress((void**)&qanh,  g_qan_h);
    cudaGetSymbolAddress((void**)&kvnh,  g_kvn_h);
    cudaGetSymbolAddress((void**)&qhp,   g_q_h);
    cudaGetSymbolAddress((void**)&kvhp,  g_kv_h);
    cudaGetSymbolAddress((void**)&krhp,  g_kr_h);
    cudaGetSymbolAddress((void**)&ath,   g_at_h);

    cudaFuncSetAttribute((const void*)tgemm2_kernel<false>,
                         cudaFuncAttributeMaxDynamicSharedMemorySize, G_SMEM);
    cudaFuncSetAttribute((const void*)tgemm2_kernel<true>,
                         cudaFuncAttributeMaxDynamicSharedMemorySize, G_SMEM);
    cudaFuncSetAttribute((const void*)attn_mma_kernel,
                         cudaFuncAttributeMaxDynamicSharedMemorySize, ATTN_SMEM);

    const dim3 blk(256);
    const int mt = NTOK / 128;

    // 0: prep (hidden convert + all weight transposes)
    prep_kernel<<<PREP_TOTAL_BLOCKS, 256>>>(hidden, wq_a, wkv_a, wq_b, wkv_b, wo);

    // 1: fused GEMM pair: qa = hid@wqa  |  ckv = hid@wkva   (fp32 out)
    {
        GemmDesc d0 = { hidh, wqah,  qa,  nullptr, Q_RANK, HIDN };
        GemmDesc d1 = { hidh, wkvah, ckv, nullptr, CKV_D,  HIDN };
        tgemm2_kernel<false><<<dim3(6 + 3, mt), blk, G_SMEM>>>(d0, d1, 6);
    }
    // 2: both rmsnorms -> fp16
    rmsnorm2_kernel<<<2 * NTOK, 256>>>(q_ln, kv_ln);
    // 3: fused GEMM pair: q = qan@wqb | kv = kvn@wkvb  (fp16 outs)
    {
        GemmDesc d0 = { qanh, wqbh,  nullptr, qhp,  QD_ALL,  Q_RANK };
        GemmDesc d1 = { kvnh, wkvbh, nullptr, kvhp, KVD_ALL, KV_RANK };
        tgemm2_kernel<true><<<dim3(30 + 40, mt), blk, G_SMEM>>>(d0, d1, 30);
    }
    // 4: rope
    rope_kernel<<<NTOK, 256>>>(qhp, ckv, krhp, cosb, sinb);
    // 5: attention (largest qt first, 3-buffer ring, 1 barrier/tile)
    attn_mma_kernel<<<dim3(SEQ / 128, 2 * NHEAD), blk, ATTN_SMEM>>>(
        qhp, kvhp, krhp, ath);
    // 6: out = attn @ wo
    {
        GemmDesc d0 = { ath, woh, out, nullptr, HIDN, OD_ALL };
        tgemm2_kernel<false><<<dim3(HIDN / 128, mt), blk, G_SMEM>>>(d0, d0, HIDN / 128);
    }
}